// round 1
// baseline (speedup 1.0000x reference)
#include <cuda_runtime.h>
#include <math.h>

#define N_GRID 4096
#define R_MS   256
#define SPLITS 16
#define KCH    (N_GRID / SPLITS)   // 256

// Scratch (no allocations allowed in kernel_launch)
__device__ float g_Cs  [R_MS * N_GRID];            // 4 MB : Cs[j][n], j = k-1
__device__ float g_part[SPLITS * 1024 * R_MS];     // 16 MB: split-K partials
__device__ float g_A   [1024 * R_MS];              // 1 MB : lam-scaled coefficients

// ---------------------------------------------------------------------------
// Accurate cos for x in [0, ~830] (immune to --use_fast_math):
// Cody-Waite 3-term pi/2 reduction + degree-8/9 minimax polys.
// ---------------------------------------------------------------------------
__device__ __forceinline__ float cos_acc(float x) {
    const float INV_PIO2 = 0.6366197723675814f;
    float qf = rintf(x * INV_PIO2);
    int   iq = (int)qf;
    const float HI = 1.57079637050628662109375f;   // fp32(pi/2)
    const float MD = -4.3711388286737929e-08f;     // pi/2 - HI
    const float LO = -1.7151245100059657e-15f;     // residual
    float r = fmaf(-qf, HI, x);
    r = fmaf(-qf, MD, r);
    r = fmaf(-qf, LO, r);
    float r2 = r * r;
    // cos(r), |r| <= pi/4
    float pc = fmaf(r2,  2.4390448796e-05f, -1.3886763775e-03f);
    pc = fmaf(r2, pc,  4.1666623323e-02f);
    pc = fmaf(r2, pc, -4.9999999725e-01f);
    pc = fmaf(r2, pc,  1.0f);
    // sin(r)
    float ps = fmaf(r2,  2.7183114939e-06f, -1.9839334836e-04f);
    ps = fmaf(r2, ps,  8.3333293859e-03f);
    ps = fmaf(r2, ps, -1.6666666642e-01f);
    ps = r * fmaf(r2 * r2 * 0.0f, 0.0f, fmaf(r2, ps, 1.0f)); // sin = r*(1 + r2*poly)
    int n = iq & 3;
    float v = (n & 1) ? ps : pc;
    if (n == 1 || n == 2) v = -v;
    return v;
}

// ---------------------------------------------------------------------------
// Kernel 0: build Cs[j][n] = sqrt(2/N) * cos(pi*(2n+1)*(j+1)/(2N))
// replicating the reference's fp32 op order: ((pi_f*(2n+1)) * k) / 8192
// ---------------------------------------------------------------------------
__global__ void build_cs_kernel() {
    int idx = blockIdx.x * blockDim.x + threadIdx.x;   // 0 .. 256*4096-1
    int j = idx >> 12;           // 0..255  (k = j+1)
    int n = idx & (N_GRID - 1);  // 0..4095
    const float PI_F = 3.1415927410125732421875f;      // fp32(pi)
    float t1 = PI_F * (float)(2 * n + 1);
    float theta = (t1 * (float)(j + 1)) * (1.0f / 8192.0f);
    const float SCALE = sqrtf(4.8828125e-4f);          // sqrt(2/4096)
    g_Cs[idx] = SCALE * cos_acc(theta);
}

// ---------------------------------------------------------------------------
// GEMM1 (split-K): part[s][b][j] = sum_{n in chunk s} rho[b][n] * Cs[j][n]
// Block tile 128(b) x 64(j), micro 8x4, K-chunk 256 per split.
// grid: (B/128, R/64, SPLITS), block 256
// ---------------------------------------------------------------------------
__global__ __launch_bounds__(256) void gemm1_kernel(const float* __restrict__ rho, int Brows) {
    __shared__ float As[8][128];   // [k][b]
    __shared__ float Bs[8][64];    // [k][j]
    const int mt = blockIdx.x, nt = blockIdx.y, s = blockIdx.z;
    const int tid = threadIdx.x;
    const int m0 = (tid >> 4) * 8;   // 0..120
    const int j0 = (tid & 15) * 4;   // 0..60

    float acc[8][4];
#pragma unroll
    for (int i = 0; i < 8; i++)
#pragma unroll
        for (int j = 0; j < 4; j++) acc[i][j] = 0.0f;

    const float* rbase = rho  + (size_t)(mt * 128) * N_GRID + s * KCH;
    const float* cbase = g_Cs + (size_t)(nt * 64)  * N_GRID + s * KCH;

    const int lr = tid >> 1;            // 0..127
    const int lc = (tid & 1) * 4;       // 0 or 4

    for (int kk = 0; kk < KCH; kk += 8) {
        float4 av = *(const float4*)(rbase + (size_t)lr * N_GRID + kk + lc);
        As[lc + 0][lr] = av.x; As[lc + 1][lr] = av.y;
        As[lc + 2][lr] = av.z; As[lc + 3][lr] = av.w;
        if (tid < 128) {
            float4 bv = *(const float4*)(cbase + (size_t)lr * N_GRID + kk + lc);
            Bs[lc + 0][lr] = bv.x; Bs[lc + 1][lr] = bv.y;
            Bs[lc + 2][lr] = bv.z; Bs[lc + 3][lr] = bv.w;
        }
        __syncthreads();
#pragma unroll
        for (int k = 0; k < 8; k++) {
            float a[8], b[4];
#pragma unroll
            for (int i = 0; i < 8; i++) a[i] = As[k][m0 + i];
#pragma unroll
            for (int j = 0; j < 4; j++) b[j] = Bs[k][j0 + j];
#pragma unroll
            for (int i = 0; i < 8; i++)
#pragma unroll
                for (int j = 0; j < 4; j++)
                    acc[i][j] = fmaf(a[i], b[j], acc[i][j]);
        }
        __syncthreads();
    }

    float* pb = g_part + ((size_t)s * Brows + mt * 128 + m0) * R_MS + nt * 64 + j0;
#pragma unroll
    for (int i = 0; i < 8; i++) {
        float4 v = make_float4(acc[i][0], acc[i][1], acc[i][2], acc[i][3]);
        *(float4*)(pb + (size_t)i * R_MS) = v;
    }
}

// ---------------------------------------------------------------------------
// Reduce split partials + lam scale: A[b][j] = ms[j] * sum_s part[s][b][j]
// ---------------------------------------------------------------------------
__global__ void reduce_lam_kernel(const float* __restrict__ ms, int Brows) {
    int idx = blockIdx.x * blockDim.x + threadIdx.x;   // 0..B*R-1
    int j = idx & (R_MS - 1);
    float sum = 0.0f;
#pragma unroll
    for (int s = 0; s < SPLITS; s++)
        sum += g_part[(size_t)s * Brows * R_MS + idx];
    g_A[idx] = ms[j] * sum;
}

// ---------------------------------------------------------------------------
// GEMM2: phi[b][n] = sum_j A[b][j] * Cs[j][n]
// Block tile 128(b) x 128(n), micro 8x8, K = 256.
// grid: (N/128, B/128), block 256
// ---------------------------------------------------------------------------
__global__ __launch_bounds__(256) void gemm2_kernel(float* __restrict__ phi) {
    __shared__ float As[8][128];   // [k][b]
    __shared__ float Bs[8][128];   // [k][n]
    const int nt = blockIdx.x, mt = blockIdx.y;
    const int tid = threadIdx.x;
    const int m0 = (tid >> 4) * 8;
    const int n0 = (tid & 15) * 8;

    float acc[8][8];
#pragma unroll
    for (int i = 0; i < 8; i++)
#pragma unroll
        for (int j = 0; j < 8; j++) acc[i][j] = 0.0f;

    const float* abase = g_A  + (size_t)(mt * 128) * R_MS;
    const float* bbase = g_Cs + nt * 128;

    const int lr  = tid >> 1;           // 0..127  (A rows)
    const int lc  = (tid & 1) * 4;      // A cols within k-chunk
    const int brj = tid >> 5;           // 0..7    (B k-row)
    const int bcn = (tid & 31) * 4;     // 0..124  (B n-col)

    for (int kk = 0; kk < R_MS; kk += 8) {
        float4 av = *(const float4*)(abase + (size_t)lr * R_MS + kk + lc);
        As[lc + 0][lr] = av.x; As[lc + 1][lr] = av.y;
        As[lc + 2][lr] = av.z; As[lc + 3][lr] = av.w;
        float4 bv = *(const float4*)(bbase + (size_t)(kk + brj) * N_GRID + bcn);
        *(float4*)(&Bs[brj][bcn]) = bv;
        __syncthreads();
#pragma unroll
        for (int k = 0; k < 8; k++) {
            float a[8], b[8];
#pragma unroll
            for (int i = 0; i < 8; i++) a[i] = As[k][m0 + i];
#pragma unroll
            for (int j = 0; j < 8; j++) b[j] = Bs[k][n0 + j];
#pragma unroll
            for (int i = 0; i < 8; i++)
#pragma unroll
                for (int j = 0; j < 8; j++)
                    acc[i][j] = fmaf(a[i], b[j], acc[i][j]);
        }
        __syncthreads();
    }

    float* ob = phi + (size_t)(mt * 128 + m0) * N_GRID + nt * 128 + n0;
#pragma unroll
    for (int i = 0; i < 8; i++) {
        *(float4*)(ob + (size_t)i * N_GRID)     = make_float4(acc[i][0], acc[i][1], acc[i][2], acc[i][3]);
        *(float4*)(ob + (size_t)i * N_GRID + 4) = make_float4(acc[i][4], acc[i][5], acc[i][6], acc[i][7]);
    }
}

// ---------------------------------------------------------------------------
extern "C" void kernel_launch(void* const* d_in, const int* in_sizes, int n_in,
                              void* d_out, int out_size) {
    const float* rho = (const float*)d_in[0];   // [B, 4096] f32
    const float* ms  = (const float*)d_in[1];   // [256] f32
    float* phi = (float*)d_out;                 // [B, 4096] f32

    const int Brows = in_sizes[0] / N_GRID;     // 1024

    build_cs_kernel<<<(R_MS * N_GRID) / 256, 256>>>();

    dim3 g1(Brows / 128, R_MS / 64, SPLITS);
    gemm1_kernel<<<g1, 256>>>(rho, Brows);

    reduce_lam_kernel<<<(Brows * R_MS) / 256, 256>>>(ms, Brows);

    dim3 g2(N_GRID / 128, Brows / 128);
    gemm2_kernel<<<g2, 256>>>(phi);
}

// round 3
// speedup vs baseline: 1.6487x; 1.6487x over previous
#include <cuda_runtime.h>
#include <cuda_bf16.h>
#include <math.h>
#include <stdint.h>

#define N_GRID 4096
#define R_MS   256
#define SPLITS 8
#define MAXB   1024

// ---------------- device scratch (no allocs allowed) ----------------
__device__ __nv_bfloat16 g_Cs_hi [R_MS * N_GRID];   // Cs[j][n] hi
__device__ __nv_bfloat16 g_Cs_lo [R_MS * N_GRID];
__device__ __nv_bfloat16 g_CsT_hi[N_GRID * R_MS];   // Cs as [n][j]
__device__ __nv_bfloat16 g_CsT_lo[N_GRID * R_MS];
__device__ float         g_part  [SPLITS * MAXB * R_MS];   // 8 MB
__device__ __nv_bfloat16 g_A_hi  [MAXB * R_MS];
__device__ __nv_bfloat16 g_A_lo  [MAXB * R_MS];

// ---------------- helpers ----------------
__device__ __forceinline__ uint32_t smem_u32(const void* p) {
    uint32_t a;
    asm("{ .reg .u64 t; cvta.to.shared.u64 t, %1; cvt.u32.u64 %0, t; }" : "=r"(a) : "l"(p));
    return a;
}
__device__ __forceinline__ uint32_t swz(uint32_t off) { return off ^ ((off >> 3) & 0x70); }

__device__ __forceinline__ void ldsm_x4(uint32_t& r0, uint32_t& r1, uint32_t& r2, uint32_t& r3,
                                        uint32_t addr) {
    asm volatile("ldmatrix.sync.aligned.m8n8.x4.shared.b16 {%0,%1,%2,%3}, [%4];"
                 : "=r"(r0), "=r"(r1), "=r"(r2), "=r"(r3) : "r"(addr));
}
__device__ __forceinline__ void ldsm_x2(uint32_t& r0, uint32_t& r1, uint32_t addr) {
    asm volatile("ldmatrix.sync.aligned.m8n8.x2.shared.b16 {%0,%1}, [%2];"
                 : "=r"(r0), "=r"(r1) : "r"(addr));
}
__device__ __forceinline__ void mma_bf16(float* c, uint32_t a0, uint32_t a1, uint32_t a2,
                                         uint32_t a3, uint32_t b0, uint32_t b1) {
    asm volatile("mma.sync.aligned.m16n8k16.row.col.f32.bf16.bf16.f32 "
                 "{%0,%1,%2,%3}, {%4,%5,%6,%7}, {%8,%9}, {%0,%1,%2,%3};"
                 : "+f"(c[0]), "+f"(c[1]), "+f"(c[2]), "+f"(c[3])
                 : "r"(a0), "r"(a1), "r"(a2), "r"(a3), "r"(b0), "r"(b1));
}

union Pack8 { __nv_bfloat16 b[8]; uint4 v; };

__device__ __forceinline__ void split2(float v, __nv_bfloat16& h, __nv_bfloat16& l) {
    h = __float2bfloat16(v);
    l = __float2bfloat16(v - __bfloat162float(h));
}

// ---------------------------------------------------------------------------
// accurate cos (verified in R1: rel_err 5e-7 end-to-end)
// ---------------------------------------------------------------------------
__device__ __forceinline__ float cos_acc(float x) {
    const float INV_PIO2 = 0.6366197723675814f;
    float qf = rintf(x * INV_PIO2);
    int   iq = (int)qf;
    const float HI = 1.57079637050628662109375f;
    const float MD = -4.3711388286737929e-08f;
    const float LO = -1.7151245100059657e-15f;
    float r = fmaf(-qf, HI, x);
    r = fmaf(-qf, MD, r);
    r = fmaf(-qf, LO, r);
    float r2 = r * r;
    float pc = fmaf(r2,  2.4390448796e-05f, -1.3886763775e-03f);
    pc = fmaf(r2, pc,  4.1666623323e-02f);
    pc = fmaf(r2, pc, -4.9999999725e-01f);
    pc = fmaf(r2, pc,  1.0f);
    float ps = fmaf(r2,  2.7183114939e-06f, -1.9839334836e-04f);
    ps = fmaf(r2, ps,  8.3333293859e-03f);
    ps = fmaf(r2, ps, -1.6666666642e-01f);
    ps = r * fmaf(r2, ps, 1.0f);
    int n = iq & 3;
    float v = (n & 1) ? ps : pc;
    if (n == 1 || n == 2) v = -v;
    return v;
}

__global__ void build_c_kernel() {
    int idx = blockIdx.x * blockDim.x + threadIdx.x;  // 0 .. 2M-1
    int which = idx >> 20;
    int r = idx & 0xFFFFF;
    int j, n;
    if (which == 0) { j = r >> 12; n = r & (N_GRID - 1); }
    else            { n = r >> 8;  j = r & (R_MS - 1);   }
    const float PI_F = 3.1415927410125732421875f;
    float t1 = PI_F * (float)(2 * n + 1);
    float theta = (t1 * (float)(j + 1)) * (1.0f / 8192.0f);
    const float SCALE = 0.02209708691f;               // sqrt(2/4096)
    float v = SCALE * cos_acc(theta);
    __nv_bfloat16 h, l;
    split2(v, h, l);
    if (which == 0) { g_Cs_hi[r]  = h; g_Cs_lo[r]  = l; }
    else            { g_CsT_hi[r] = h; g_CsT_lo[r] = l; }
}

// ---------------------------------------------------------------------------
// smem: 4 tiles of 128 rows x 64 bf16 (128B swizzled rows) = 16KB each
//   [0]=A_hi  [16384]=A_lo  [32768]=B_hi  [49152]=B_lo      total 64KB
// ---------------------------------------------------------------------------
#define SM_AH 0
#define SM_AL 16384
#define SM_BH 32768
#define SM_BL 49152
#define SMEM_BYTES 65536

// compute phase shared by both gemms: 128x128 tile, one 64-wide K step
__device__ __forceinline__ void compute_step(uint32_t sb, int wm, int wn, int lane,
                                             float acc[4][4][4]) {
    const uint32_t aRow = (uint32_t)(wm * 64 + (lane & 15)) * 128 + ((lane >> 4) << 4);
    const uint32_t bRow = (uint32_t)(wn * 32 + (lane & 7)) * 128 + (((lane >> 3) & 1) << 4);
#pragma unroll
    for (int k16 = 0; k16 < 4; k16++) {
        const uint32_t kb = k16 * 32;
        uint32_t aH[4][4], aL[4][4];
#pragma unroll
        for (int mi = 0; mi < 4; mi++) {
            uint32_t off = swz(aRow + mi * 16 * 128 + kb);
            ldsm_x4(aH[mi][0], aH[mi][1], aH[mi][2], aH[mi][3], sb + SM_AH + off);
            ldsm_x4(aL[mi][0], aL[mi][1], aL[mi][2], aL[mi][3], sb + SM_AL + off);
        }
        uint32_t bH[4][2], bL[4][2];
#pragma unroll
        for (int nj = 0; nj < 4; nj++) {
            uint32_t off = swz(bRow + nj * 8 * 128 + kb);
            ldsm_x2(bH[nj][0], bH[nj][1], sb + SM_BH + off);
            ldsm_x2(bL[nj][0], bL[nj][1], sb + SM_BL + off);
        }
#pragma unroll
        for (int mi = 0; mi < 4; mi++)
#pragma unroll
            for (int nj = 0; nj < 4; nj++) {
                float* c = acc[mi][nj];
                mma_bf16(c, aH[mi][0], aH[mi][1], aH[mi][2], aH[mi][3], bH[nj][0], bH[nj][1]);
                mma_bf16(c, aH[mi][0], aH[mi][1], aH[mi][2], aH[mi][3], bL[nj][0], bL[nj][1]);
                mma_bf16(c, aL[mi][0], aL[mi][1], aL[mi][2], aL[mi][3], bH[nj][0], bH[nj][1]);
            }
    }
}

// ---------------------------------------------------------------------------
// GEMM1: part[sp][b][j] = sum_{k in chunk} rho[b][k] * Cs[j][k]
// grid (B/128, 256/128, SPLITS), block 256
// ---------------------------------------------------------------------------
__global__ __launch_bounds__(256) void gemm1_hmma(const float* __restrict__ rho, int Brows) {
    extern __shared__ char sm[];
    const uint32_t sb = smem_u32(sm);
    const int tid = threadIdx.x, wid = tid >> 5, lane = tid & 31;
    const int wm = wid & 1, wn = wid >> 1;
    const int mt = blockIdx.x, nt = blockIdx.y, sp = blockIdx.z;
    const int k0 = sp * (N_GRID / SPLITS);             // 512-chunk

    float acc[4][4][4];
#pragma unroll
    for (int a = 0; a < 4; a++)
#pragma unroll
        for (int b = 0; b < 4; b++)
#pragma unroll
            for (int c = 0; c < 4; c++) acc[a][b][c] = 0.0f;

    const int arow = tid >> 1, ahalf = tid & 1;                 // A fill: 2 thr/row
    const int bop = tid >> 7, brow = tid & 127;                 // B fill: 1 thr/row/op

    for (int step = 0; step < (N_GRID / SPLITS) / 64; step++) {
        // A: rho fp32 -> hi/lo bf16
        {
            const float4* src = (const float4*)(rho + (size_t)(mt * 128 + arow) * N_GRID
                                                + k0 + step * 64 + ahalf * 32);
#pragma unroll
            for (int i = 0; i < 4; i++) {
                float4 f0 = src[2 * i], f1 = src[2 * i + 1];
                float vals[8] = {f0.x, f0.y, f0.z, f0.w, f1.x, f1.y, f1.z, f1.w};
                Pack8 ph, pl;
#pragma unroll
                for (int e = 0; e < 8; e++) split2(vals[e], ph.b[e], pl.b[e]);
                uint32_t off = swz((uint32_t)arow * 128 + ahalf * 64 + i * 16);
                *(uint4*)(sm + SM_AH + off) = ph.v;
                *(uint4*)(sm + SM_AL + off) = pl.v;
            }
        }
        // B: Cs rows (j = nt*128 + brow), hi or lo by bop
        {
            const uint4* src = (const uint4*)((bop ? g_Cs_lo : g_Cs_hi)
                                              + (size_t)(nt * 128 + brow) * N_GRID + k0 + step * 64);
            char* dst = sm + (bop ? SM_BL : SM_BH);
#pragma unroll
            for (int i = 0; i < 8; i++)
                *(uint4*)(dst + swz((uint32_t)brow * 128 + i * 16)) = src[i];
        }
        __syncthreads();
        compute_step(sb, wm, wn, lane, acc);
        __syncthreads();
    }

    // epilogue -> g_part fp32
    const int g = lane >> 2, tig = lane & 3;
    const int mbase = mt * 128 + wm * 64;
    const int nbase = nt * 128 + wn * 32;
#pragma unroll
    for (int mi = 0; mi < 4; mi++)
#pragma unroll
        for (int nj = 0; nj < 4; nj++) {
            int row = mbase + mi * 16 + g;
            int col = nbase + nj * 8 + tig * 2;
            float* p0 = g_part + ((size_t)sp * Brows + row) * R_MS + col;
            *(float2*)p0                    = make_float2(acc[mi][nj][0], acc[mi][nj][1]);
            *(float2*)(p0 + 8 * R_MS)       = make_float2(acc[mi][nj][2], acc[mi][nj][3]);
        }
}

// reduce splits + lam scale -> bf16 hi/lo coefficients
__global__ void reduce_lam_kernel(const float* __restrict__ ms, int Brows) {
    int idx = blockIdx.x * blockDim.x + threadIdx.x;  // 0..B*256-1
    int j = idx & (R_MS - 1);
    float sum = 0.0f;
#pragma unroll
    for (int s = 0; s < SPLITS; s++)
        sum += g_part[(size_t)s * Brows * R_MS + idx];
    float v = ms[j] * sum;
    __nv_bfloat16 h, l;
    split2(v, h, l);
    g_A_hi[idx] = h;
    g_A_lo[idx] = l;
}

// ---------------------------------------------------------------------------
// GEMM2: phi[b][n] = sum_j A[b][j] * CsT[n][j]
// grid (B/128, 4096/128), block 256, K = 256 (4 steps)
// ---------------------------------------------------------------------------
__global__ __launch_bounds__(256) void gemm2_hmma(float* __restrict__ phi, int Brows) {
    extern __shared__ char sm[];
    const uint32_t sb = smem_u32(sm);
    const int tid = threadIdx.x, wid = tid >> 5, lane = tid & 31;
    const int wm = wid & 1, wn = wid >> 1;
    const int mt = blockIdx.x, nt = blockIdx.y;

    float acc[4][4][4];
#pragma unroll
    for (int a = 0; a < 4; a++)
#pragma unroll
        for (int b = 0; b < 4; b++)
#pragma unroll
            for (int c = 0; c < 4; c++) acc[a][b][c] = 0.0f;

    const int op = tid >> 7, row = tid & 127;

    for (int step = 0; step < R_MS / 64; step++) {
        // A: g_A hi/lo bf16 rows
        {
            const uint4* src = (const uint4*)((op ? g_A_lo : g_A_hi)
                                              + (size_t)(mt * 128 + row) * R_MS + step * 64);
            char* dst = sm + (op ? SM_AL : SM_AH);
#pragma unroll
            for (int i = 0; i < 8; i++)
                *(uint4*)(dst + swz((uint32_t)row * 128 + i * 16)) = src[i];
        }
        // B: CsT rows (n = nt*128 + row)
        {
            const uint4* src = (const uint4*)((op ? g_CsT_lo : g_CsT_hi)
                                              + (size_t)(nt * 128 + row) * R_MS + step * 64);
            char* dst = sm + (op ? SM_BL : SM_BH);
#pragma unroll
            for (int i = 0; i < 8; i++)
                *(uint4*)(dst + swz((uint32_t)row * 128 + i * 16)) = src[i];
        }
        __syncthreads();
        compute_step(sb, wm, wn, lane, acc);
        __syncthreads();
    }

    // epilogue -> phi fp32
    const int g = lane >> 2, tig = lane & 3;
    const int mbase = mt * 128 + wm * 64;
    const int nbase = nt * 128 + wn * 32;
#pragma unroll
    for (int mi = 0; mi < 4; mi++)
#pragma unroll
        for (int nj = 0; nj < 4; nj++) {
            int r = mbase + mi * 16 + g;
            int c = nbase + nj * 8 + tig * 2;
            float* p0 = phi + (size_t)r * N_GRID + c;
            *(float2*)p0                 = make_float2(acc[mi][nj][0], acc[mi][nj][1]);
            *(float2*)(p0 + 8 * N_GRID)  = make_float2(acc[mi][nj][2], acc[mi][nj][3]);
        }
}

// ---------------------------------------------------------------------------
extern "C" void kernel_launch(void* const* d_in, const int* in_sizes, int n_in,
                              void* d_out, int out_size) {
    const float* rho = (const float*)d_in[0];   // [B, 4096] f32
    const float* ms  = (const float*)d_in[1];   // [256] f32
    float* phi = (float*)d_out;                 // [B, 4096] f32
    const int Brows = in_sizes[0] / N_GRID;     // 1024

    cudaFuncSetAttribute(gemm1_hmma, cudaFuncAttributeMaxDynamicSharedMemorySize, SMEM_BYTES);
    cudaFuncSetAttribute(gemm2_hmma, cudaFuncAttributeMaxDynamicSharedMemorySize, SMEM_BYTES);

    build_c_kernel<<<(2 * R_MS * N_GRID) / 256, 256>>>();

    dim3 g1(Brows / 128, R_MS / 128, SPLITS);
    gemm1_hmma<<<g1, 256, SMEM_BYTES>>>(rho, Brows);

    reduce_lam_kernel<<<(Brows * R_MS) / 256, 256>>>(ms, Brows);

    dim3 g2(Brows / 128, N_GRID / 128);
    gemm2_hmma<<<g2, 256, SMEM_BYTES>>>(phi, Brows);
}

// round 4
// speedup vs baseline: 2.1850x; 1.3253x over previous
#include <cuda_runtime.h>
#include <cuda_bf16.h>
#include <math.h>
#include <stdint.h>

#define N_GRID 4096
#define R_MS   256
#define SPLITS 8
#define MAXB   1024

// ---------------- device scratch (no allocs allowed) ----------------
__device__ __nv_bfloat16 g_rho_hi[MAXB * N_GRID];   // 8 MB
__device__ __nv_bfloat16 g_rho_lo[MAXB * N_GRID];   // 8 MB
__device__ __nv_bfloat16 g_Cs_hi [R_MS * N_GRID];   // Cs[j][n] hi
__device__ __nv_bfloat16 g_Cs_lo [R_MS * N_GRID];
__device__ __nv_bfloat16 g_CsT_hi[N_GRID * R_MS];   // Cs as [n][j]
__device__ __nv_bfloat16 g_CsT_lo[N_GRID * R_MS];
__device__ float         g_part  [SPLITS * MAXB * R_MS];   // 8 MB
__device__ __nv_bfloat16 g_A_hi  [MAXB * R_MS];
__device__ __nv_bfloat16 g_A_lo  [MAXB * R_MS];

// ---------------- helpers ----------------
__device__ __forceinline__ uint32_t smem_u32(const void* p) {
    uint32_t a;
    asm("{ .reg .u64 t; cvta.to.shared.u64 t, %1; cvt.u32.u64 %0, t; }" : "=r"(a) : "l"(p));
    return a;
}
__device__ __forceinline__ uint32_t swz(uint32_t off) { return off ^ ((off >> 3) & 0x70); }

__device__ __forceinline__ void cp16(uint32_t dst, const void* src) {
    asm volatile("cp.async.cg.shared.global [%0], [%1], 16;" :: "r"(dst), "l"(src));
}
__device__ __forceinline__ void cp_commit() {
    asm volatile("cp.async.commit_group;" ::: "memory");
}
template <int N>
__device__ __forceinline__ void cp_wait() {
    asm volatile("cp.async.wait_group %0;" :: "n"(N) : "memory");
}

__device__ __forceinline__ void ldsm_x4(uint32_t& r0, uint32_t& r1, uint32_t& r2, uint32_t& r3,
                                        uint32_t addr) {
    asm volatile("ldmatrix.sync.aligned.m8n8.x4.shared.b16 {%0,%1,%2,%3}, [%4];"
                 : "=r"(r0), "=r"(r1), "=r"(r2), "=r"(r3) : "r"(addr));
}
__device__ __forceinline__ void ldsm_x2(uint32_t& r0, uint32_t& r1, uint32_t addr) {
    asm volatile("ldmatrix.sync.aligned.m8n8.x2.shared.b16 {%0,%1}, [%2];"
                 : "=r"(r0), "=r"(r1) : "r"(addr));
}
__device__ __forceinline__ void mma_bf16(float* c, uint32_t a0, uint32_t a1, uint32_t a2,
                                         uint32_t a3, uint32_t b0, uint32_t b1) {
    asm volatile("mma.sync.aligned.m16n8k16.row.col.f32.bf16.bf16.f32 "
                 "{%0,%1,%2,%3}, {%4,%5,%6,%7}, {%8,%9}, {%0,%1,%2,%3};"
                 : "+f"(c[0]), "+f"(c[1]), "+f"(c[2]), "+f"(c[3])
                 : "r"(a0), "r"(a1), "r"(a2), "r"(a3), "r"(b0), "r"(b1));
}

__device__ __forceinline__ void split2(float v, __nv_bfloat16& h, __nv_bfloat16& l) {
    h = __float2bfloat16(v);
    l = __float2bfloat16(v - __bfloat162float(h));
}

// ---------------------------------------------------------------------------
// accurate cos (verified: rel_err ~7e-6 end-to-end)
// ---------------------------------------------------------------------------
__device__ __forceinline__ float cos_acc(float x) {
    const float INV_PIO2 = 0.6366197723675814f;
    float qf = rintf(x * INV_PIO2);
    int   iq = (int)qf;
    const float HI = 1.57079637050628662109375f;
    const float MD = -4.3711388286737929e-08f;
    const float LO = -1.7151245100059657e-15f;
    float r = fmaf(-qf, HI, x);
    r = fmaf(-qf, MD, r);
    r = fmaf(-qf, LO, r);
    float r2 = r * r;
    float pc = fmaf(r2,  2.4390448796e-05f, -1.3886763775e-03f);
    pc = fmaf(r2, pc,  4.1666623323e-02f);
    pc = fmaf(r2, pc, -4.9999999725e-01f);
    pc = fmaf(r2, pc,  1.0f);
    float ps = fmaf(r2,  2.7183114939e-06f, -1.9839334836e-04f);
    ps = fmaf(r2, ps,  8.3333293859e-03f);
    ps = fmaf(r2, ps, -1.6666666642e-01f);
    ps = r * fmaf(r2, ps, 1.0f);
    int n = iq & 3;
    float v = (n & 1) ? ps : pc;
    if (n == 1 || n == 2) v = -v;
    return v;
}

// ---------------------------------------------------------------------------
// prep kernel: blocks [0, 4096) convert rho -> hi/lo (4 f32 per thread)
//              blocks [4096, 12288) build Cs / CsT hi+lo
// ---------------------------------------------------------------------------
__global__ void prep_kernel(const float* __restrict__ rho) {
    int bx = blockIdx.x;
    if (bx < 4096) {
        int t = bx * 256 + threadIdx.x;          // 0 .. 1M-1, 4 elems each
        float4 f = ((const float4*)rho)[t];
        __nv_bfloat16 h[4], l[4];
        split2(f.x, h[0], l[0]); split2(f.y, h[1], l[1]);
        split2(f.z, h[2], l[2]); split2(f.w, h[3], l[3]);
        ((uint2*)g_rho_hi)[t] = *(uint2*)h;
        ((uint2*)g_rho_lo)[t] = *(uint2*)l;
    } else {
        int idx = (bx - 4096) * 256 + threadIdx.x;   // 0 .. 2M-1
        int which = idx >> 20;
        int r = idx & 0xFFFFF;
        int j, n;
        if (which == 0) { j = r >> 12; n = r & (N_GRID - 1); }
        else            { n = r >> 8;  j = r & (R_MS - 1);   }
        const float PI_F = 3.1415927410125732421875f;
        float t1 = PI_F * (float)(2 * n + 1);
        float theta = (t1 * (float)(j + 1)) * (1.0f / 8192.0f);
        const float SCALE = 0.02209708691f;          // sqrt(2/4096)
        float v = SCALE * cos_acc(theta);
        __nv_bfloat16 h, l;
        split2(v, h, l);
        if (which == 0) { g_Cs_hi[r]  = h; g_Cs_lo[r]  = l; }
        else            { g_CsT_hi[r] = h; g_CsT_lo[r] = l; }
    }
}

// ---------------------------------------------------------------------------
// smem: 2 stages x 4 tiles of 128 rows x 64 bf16 (swizzled 128B rows)
//   stage offset = stage*65536 ; within: AH=0 AL=16384 BH=32768 BL=49152
// ---------------------------------------------------------------------------
#define STG    65536
#define SM_AL  16384
#define SM_BH  32768
#define SM_BL  49152
#define SMEM_BYTES (2 * STG)

// async fill of one 128x64 bf16 tile; src pre-offset to tile origin
__device__ __forceinline__ void tile_async(uint32_t dst, const __nv_bfloat16* src,
                                           int stride, int tid) {
    const int row = tid >> 1;
    const int c0 = (tid & 1) * 4;
    const char* s = (const char*)(src + (size_t)row * stride);
#pragma unroll
    for (int i = 0; i < 4; i++) {
        int ch = c0 + i;
        cp16(dst + swz((uint32_t)row * 128 + ch * 16), s + ch * 16);
    }
}

// compute one 64-wide K step on a 128x128 tile (3-term bf16)
__device__ __forceinline__ void compute_step(uint32_t st, int wm, int wn, int lane,
                                             float acc[4][4][4]) {
    const uint32_t aRow = (uint32_t)(wm * 64 + (lane & 15)) * 128 + ((lane >> 4) << 4);
    const uint32_t bRow = (uint32_t)(wn * 32 + (lane & 7)) * 128 + (((lane >> 3) & 1) << 4);
#pragma unroll
    for (int k16 = 0; k16 < 4; k16++) {
        const uint32_t kb = k16 * 32;
        uint32_t aH[4][4], aL[4][4];
#pragma unroll
        for (int mi = 0; mi < 4; mi++) {
            uint32_t off = swz(aRow + mi * 16 * 128 + kb);
            ldsm_x4(aH[mi][0], aH[mi][1], aH[mi][2], aH[mi][3], st + off);
            ldsm_x4(aL[mi][0], aL[mi][1], aL[mi][2], aL[mi][3], st + SM_AL + off);
        }
        uint32_t bH[4][2], bL[4][2];
#pragma unroll
        for (int nj = 0; nj < 4; nj++) {
            uint32_t off = swz(bRow + nj * 8 * 128 + kb);
            ldsm_x2(bH[nj][0], bH[nj][1], st + SM_BH + off);
            ldsm_x2(bL[nj][0], bL[nj][1], st + SM_BL + off);
        }
#pragma unroll
        for (int mi = 0; mi < 4; mi++)
#pragma unroll
            for (int nj = 0; nj < 4; nj++) {
                float* c = acc[mi][nj];
                mma_bf16(c, aH[mi][0], aH[mi][1], aH[mi][2], aH[mi][3], bH[nj][0], bH[nj][1]);
                mma_bf16(c, aH[mi][0], aH[mi][1], aH[mi][2], aH[mi][3], bL[nj][0], bL[nj][1]);
                mma_bf16(c, aL[mi][0], aL[mi][1], aL[mi][2], aL[mi][3], bH[nj][0], bH[nj][1]);
            }
    }
}

// ---------------------------------------------------------------------------
// GEMM1: part[sp][b][j] = sum_{k chunk} rho[b][k] * Cs[j][k]
// grid (B/128, 256/128, SPLITS), block 256; K-chunk 512 (8 steps)
// ---------------------------------------------------------------------------
__global__ __launch_bounds__(256) void gemm1_hmma(int Brows) {
    extern __shared__ char sm[];
    const uint32_t sb = smem_u32(sm);
    const int tid = threadIdx.x, wid = tid >> 5, lane = tid & 31;
    const int wm = wid & 1, wn = wid >> 1;
    const int mt = blockIdx.x, nt = blockIdx.y, sp = blockIdx.z;
    const int k0 = sp * (N_GRID / SPLITS);
    const int NS = (N_GRID / SPLITS) / 64;           // 8

    float acc[4][4][4];
#pragma unroll
    for (int a = 0; a < 4; a++)
#pragma unroll
        for (int b = 0; b < 4; b++)
#pragma unroll
            for (int c = 0; c < 4; c++) acc[a][b][c] = 0.0f;

    const __nv_bfloat16* aHsrc = g_rho_hi + (size_t)(mt * 128) * N_GRID + k0;
    const __nv_bfloat16* aLsrc = g_rho_lo + (size_t)(mt * 128) * N_GRID + k0;
    const __nv_bfloat16* bHsrc = g_Cs_hi  + (size_t)(nt * 128) * N_GRID + k0;
    const __nv_bfloat16* bLsrc = g_Cs_lo  + (size_t)(nt * 128) * N_GRID + k0;

    // prologue: prefetch step 0 into stage 0
    {
        uint32_t st = sb;
        tile_async(st,         aHsrc, N_GRID, tid);
        tile_async(st + SM_AL, aLsrc, N_GRID, tid);
        tile_async(st + SM_BH, bHsrc, N_GRID, tid);
        tile_async(st + SM_BL, bLsrc, N_GRID, tid);
        cp_commit();
    }
    for (int s = 0; s < NS; s++) {
        if (s + 1 < NS) {
            uint32_t st = sb + ((s + 1) & 1) * STG;
            int ko = (s + 1) * 64;
            tile_async(st,         aHsrc + ko, N_GRID, tid);
            tile_async(st + SM_AL, aLsrc + ko, N_GRID, tid);
            tile_async(st + SM_BH, bHsrc + ko, N_GRID, tid);
            tile_async(st + SM_BL, bLsrc + ko, N_GRID, tid);
            cp_commit();
            cp_wait<1>();
        } else {
            cp_wait<0>();
        }
        __syncthreads();
        compute_step(sb + (s & 1) * STG, wm, wn, lane, acc);
        __syncthreads();
    }

    const int g = lane >> 2, tig = lane & 3;
    const int mbase = mt * 128 + wm * 64;
    const int nbase = nt * 128 + wn * 32;
#pragma unroll
    for (int mi = 0; mi < 4; mi++)
#pragma unroll
        for (int nj = 0; nj < 4; nj++) {
            int row = mbase + mi * 16 + g;
            int col = nbase + nj * 8 + tig * 2;
            float* p0 = g_part + ((size_t)sp * Brows + row) * R_MS + col;
            *(float2*)p0              = make_float2(acc[mi][nj][0], acc[mi][nj][1]);
            *(float2*)(p0 + 8 * R_MS) = make_float2(acc[mi][nj][2], acc[mi][nj][3]);
        }
}

// reduce splits + lam scale -> bf16 hi/lo coefficients
__global__ void reduce_lam_kernel(const float* __restrict__ ms, int Brows) {
    int idx = blockIdx.x * blockDim.x + threadIdx.x;
    int j = idx & (R_MS - 1);
    float sum = 0.0f;
#pragma unroll
    for (int s = 0; s < SPLITS; s++)
        sum += g_part[(size_t)s * Brows * R_MS + idx];
    float v = ms[j] * sum;
    __nv_bfloat16 h, l;
    split2(v, h, l);
    g_A_hi[idx] = h;
    g_A_lo[idx] = l;
}

// ---------------------------------------------------------------------------
// GEMM2: phi[b][n] = sum_j A[b][j] * CsT[n][j]
// grid (B/128, 4096/128), block 256; K = 256 (4 steps)
// ---------------------------------------------------------------------------
__global__ __launch_bounds__(256) void gemm2_hmma(float* __restrict__ phi) {
    extern __shared__ char sm[];
    const uint32_t sb = smem_u32(sm);
    const int tid = threadIdx.x, wid = tid >> 5, lane = tid & 31;
    const int wm = wid & 1, wn = wid >> 1;
    const int mt = blockIdx.x, nt = blockIdx.y;
    const int NS = R_MS / 64;                        // 4

    float acc[4][4][4];
#pragma unroll
    for (int a = 0; a < 4; a++)
#pragma unroll
        for (int b = 0; b < 4; b++)
#pragma unroll
            for (int c = 0; c < 4; c++) acc[a][b][c] = 0.0f;

    const __nv_bfloat16* aHsrc = g_A_hi   + (size_t)(mt * 128) * R_MS;
    const __nv_bfloat16* aLsrc = g_A_lo   + (size_t)(mt * 128) * R_MS;
    const __nv_bfloat16* bHsrc = g_CsT_hi + (size_t)(nt * 128) * R_MS;
    const __nv_bfloat16* bLsrc = g_CsT_lo + (size_t)(nt * 128) * R_MS;

    {
        uint32_t st = sb;
        tile_async(st,         aHsrc, R_MS, tid);
        tile_async(st + SM_AL, aLsrc, R_MS, tid);
        tile_async(st + SM_BH, bHsrc, R_MS, tid);
        tile_async(st + SM_BL, bLsrc, R_MS, tid);
        cp_commit();
    }
    for (int s = 0; s < NS; s++) {
        if (s + 1 < NS) {
            uint32_t st = sb + ((s + 1) & 1) * STG;
            int ko = (s + 1) * 64;
            tile_async(st,         aHsrc + ko, R_MS, tid);
            tile_async(st + SM_AL, aLsrc + ko, R_MS, tid);
            tile_async(st + SM_BH, bHsrc + ko, R_MS, tid);
            tile_async(st + SM_BL, bLsrc + ko, R_MS, tid);
            cp_commit();
            cp_wait<1>();
        } else {
            cp_wait<0>();
        }
        __syncthreads();
        compute_step(sb + (s & 1) * STG, wm, wn, lane, acc);
        __syncthreads();
    }

    const int g = lane >> 2, tig = lane & 3;
    const int mbase = mt * 128 + wm * 64;
    const int nbase = nt * 128 + wn * 32;
#pragma unroll
    for (int mi = 0; mi < 4; mi++)
#pragma unroll
        for (int nj = 0; nj < 4; nj++) {
            int r = mbase + mi * 16 + g;
            int c = nbase + nj * 8 + tig * 2;
            float* p0 = phi + (size_t)r * N_GRID + c;
            *(float2*)p0                = make_float2(acc[mi][nj][0], acc[mi][nj][1]);
            *(float2*)(p0 + 8 * N_GRID) = make_float2(acc[mi][nj][2], acc[mi][nj][3]);
        }
}

// ---------------------------------------------------------------------------
extern "C" void kernel_launch(void* const* d_in, const int* in_sizes, int n_in,
                              void* d_out, int out_size) {
    const float* rho = (const float*)d_in[0];   // [B, 4096] f32
    const float* ms  = (const float*)d_in[1];   // [256] f32
    float* phi = (float*)d_out;                 // [B, 4096] f32
    const int Brows = in_sizes[0] / N_GRID;     // 1024

    cudaFuncSetAttribute(gemm1_hmma, cudaFuncAttributeMaxDynamicSharedMemorySize, SMEM_BYTES);
    cudaFuncSetAttribute(gemm2_hmma, cudaFuncAttributeMaxDynamicSharedMemorySize, SMEM_BYTES);

    prep_kernel<<<12288, 256>>>(rho);

    dim3 g1(Brows / 128, R_MS / 128, SPLITS);
    gemm1_hmma<<<g1, 256, SMEM_BYTES>>>(Brows);

    reduce_lam_kernel<<<(Brows * R_MS) / 256, 256>>>(ms, Brows);

    dim3 g2(Brows / 128, N_GRID / 128);
    gemm2_hmma<<<g2, 256, SMEM_BYTES>>>(phi);
}

// round 5
// speedup vs baseline: 2.4449x; 1.1189x over previous
#include <cuda_runtime.h>
#include <cuda_bf16.h>
#include <math.h>
#include <stdint.h>

#define N_GRID 4096
#define R_MS   256
#define SPLITS 8
#define MAXB   1024

// ---------------- device scratch ----------------
__device__ __nv_bfloat16 g_rho_hi[MAXB * N_GRID];
__device__ __nv_bfloat16 g_rho_lo[MAXB * N_GRID];
__device__ __nv_bfloat16 g_Cs_hi [R_MS * N_GRID];
__device__ __nv_bfloat16 g_Cs_lo [R_MS * N_GRID];
__device__ __nv_bfloat16 g_CsT_hi[N_GRID * R_MS];
__device__ __nv_bfloat16 g_CsT_lo[N_GRID * R_MS];
__device__ float         g_part  [SPLITS * MAXB * R_MS];
__device__ __nv_bfloat16 g_A_hi  [MAXB * R_MS];
__device__ __nv_bfloat16 g_A_lo  [MAXB * R_MS];

// ---------------- helpers ----------------
__device__ __forceinline__ uint32_t smem_u32(const void* p) {
    uint32_t a;
    asm("{ .reg .u64 t; cvta.to.shared.u64 t, %1; cvt.u32.u64 %0, t; }" : "=r"(a) : "l"(p));
    return a;
}
__device__ __forceinline__ uint32_t swz(uint32_t off) { return off ^ ((off >> 3) & 0x70); }

__device__ __forceinline__ void cp16(uint32_t dst, const void* src) {
    asm volatile("cp.async.cg.shared.global [%0], [%1], 16;" :: "r"(dst), "l"(src));
}
__device__ __forceinline__ void cp_commit() {
    asm volatile("cp.async.commit_group;" ::: "memory");
}
template <int N>
__device__ __forceinline__ void cp_wait() {
    asm volatile("cp.async.wait_group %0;" :: "n"(N) : "memory");
}

__device__ __forceinline__ void ldsm_x4(uint32_t& r0, uint32_t& r1, uint32_t& r2, uint32_t& r3,
                                        uint32_t addr) {
    asm volatile("ldmatrix.sync.aligned.m8n8.x4.shared.b16 {%0,%1,%2,%3}, [%4];"
                 : "=r"(r0), "=r"(r1), "=r"(r2), "=r"(r3) : "r"(addr));
}
__device__ __forceinline__ void ldsm_x2(uint32_t& r0, uint32_t& r1, uint32_t addr) {
    asm volatile("ldmatrix.sync.aligned.m8n8.x2.shared.b16 {%0,%1}, [%2];"
                 : "=r"(r0), "=r"(r1) : "r"(addr));
}
__device__ __forceinline__ void mma_bf16(float* c, uint32_t a0, uint32_t a1, uint32_t a2,
                                         uint32_t a3, uint32_t b0, uint32_t b1) {
    asm volatile("mma.sync.aligned.m16n8k16.row.col.f32.bf16.bf16.f32 "
                 "{%0,%1,%2,%3}, {%4,%5,%6,%7}, {%8,%9}, {%0,%1,%2,%3};"
                 : "+f"(c[0]), "+f"(c[1]), "+f"(c[2]), "+f"(c[3])
                 : "r"(a0), "r"(a1), "r"(a2), "r"(a3), "r"(b0), "r"(b1));
}

__device__ __forceinline__ void split2(float v, __nv_bfloat16& h, __nv_bfloat16& l) {
    h = __float2bfloat16(v);
    l = __float2bfloat16(v - __bfloat162float(h));
}

// ---------------------------------------------------------------------------
__device__ __forceinline__ float cos_acc(float x) {
    const float INV_PIO2 = 0.6366197723675814f;
    float qf = rintf(x * INV_PIO2);
    int   iq = (int)qf;
    const float HI = 1.57079637050628662109375f;
    const float MD = -4.3711388286737929e-08f;
    const float LO = -1.7151245100059657e-15f;
    float r = fmaf(-qf, HI, x);
    r = fmaf(-qf, MD, r);
    r = fmaf(-qf, LO, r);
    float r2 = r * r;
    float pc = fmaf(r2,  2.4390448796e-05f, -1.3886763775e-03f);
    pc = fmaf(r2, pc,  4.1666623323e-02f);
    pc = fmaf(r2, pc, -4.9999999725e-01f);
    pc = fmaf(r2, pc,  1.0f);
    float ps = fmaf(r2,  2.7183114939e-06f, -1.9839334836e-04f);
    ps = fmaf(r2, ps,  8.3333293859e-03f);
    ps = fmaf(r2, ps, -1.6666666642e-01f);
    ps = r * fmaf(r2, ps, 1.0f);
    int n = iq & 3;
    float v = (n & 1) ? ps : pc;
    if (n == 1 || n == 2) v = -v;
    return v;
}

__global__ void prep_kernel(const float* __restrict__ rho) {
    int bx = blockIdx.x;
    if (bx < 4096) {
        int t = bx * 256 + threadIdx.x;
        float4 f = ((const float4*)rho)[t];
        __nv_bfloat16 h[4], l[4];
        split2(f.x, h[0], l[0]); split2(f.y, h[1], l[1]);
        split2(f.z, h[2], l[2]); split2(f.w, h[3], l[3]);
        ((uint2*)g_rho_hi)[t] = *(uint2*)h;
        ((uint2*)g_rho_lo)[t] = *(uint2*)l;
    } else {
        int idx = (bx - 4096) * 256 + threadIdx.x;
        int which = idx >> 20;
        int r = idx & 0xFFFFF;
        int j, n;
        if (which == 0) { j = r >> 12; n = r & (N_GRID - 1); }
        else            { n = r >> 8;  j = r & (R_MS - 1);   }
        const float PI_F = 3.1415927410125732421875f;
        float t1 = PI_F * (float)(2 * n + 1);
        float theta = (t1 * (float)(j + 1)) * (1.0f / 8192.0f);
        const float SCALE = 0.02209708691f;
        float v = SCALE * cos_acc(theta);
        __nv_bfloat16 h, l;
        split2(v, h, l);
        if (which == 0) { g_Cs_hi[r]  = h; g_Cs_lo[r]  = l; }
        else            { g_CsT_hi[r] = h; g_CsT_lo[r] = l; }
    }
}

// ---------------------------------------------------------------------------
// smem: 2 stages x { AH, AL, BH, BL } each 128 rows x 64 bf16 swizzled = 16KB
// ---------------------------------------------------------------------------
#define STG    65536
#define SM_AL  16384
#define SM_BH  32768
#define SM_BL  49152
#define SMEM_BYTES (2 * STG)

// async fill of a 128x64 bf16 tile using 512 threads (2 cp16 each)
__device__ __forceinline__ void tile_async(uint32_t dst, const __nv_bfloat16* src,
                                           int stride, int tid) {
    const int row = tid >> 2;
    const int c0 = tid & 3;
    const char* s = (const char*)(src + (size_t)row * stride);
#pragma unroll
    for (int i = 0; i < 2; i++) {
        int ch = c0 + i * 4;
        cp16(dst + swz((uint32_t)row * 128 + ch * 16), s + ch * 16);
    }
}

// one 64-wide K step; warp tile 32x32 within 128x128 block tile, 16 warps 4x4
__device__ __forceinline__ void compute_step(uint32_t st, int wm, int wn, int lane,
                                             float acc[2][4][4]) {
    const uint32_t aRow = (uint32_t)(wm * 32 + (lane & 15)) * 128 + ((lane >> 4) << 4);
    const uint32_t bRow = (uint32_t)(wn * 32 + (lane & 7)) * 128 + (((lane >> 3) & 1) << 4);
#pragma unroll
    for (int k16 = 0; k16 < 4; k16++) {
        const uint32_t kb = k16 * 32;
        uint32_t aH[2][4], aL[2][4];
#pragma unroll
        for (int mi = 0; mi < 2; mi++) {
            uint32_t off = swz(aRow + mi * 16 * 128 + kb);
            ldsm_x4(aH[mi][0], aH[mi][1], aH[mi][2], aH[mi][3], st + off);
            ldsm_x4(aL[mi][0], aL[mi][1], aL[mi][2], aL[mi][3], st + SM_AL + off);
        }
        uint32_t bH[4][2], bL[4][2];
#pragma unroll
        for (int nj = 0; nj < 4; nj++) {
            uint32_t off = swz(bRow + nj * 8 * 128 + kb);
            ldsm_x2(bH[nj][0], bH[nj][1], st + SM_BH + off);
            ldsm_x2(bL[nj][0], bL[nj][1], st + SM_BL + off);
        }
#pragma unroll
        for (int mi = 0; mi < 2; mi++)
#pragma unroll
            for (int nj = 0; nj < 4; nj++) {
                float* c = acc[mi][nj];
                mma_bf16(c, aH[mi][0], aH[mi][1], aH[mi][2], aH[mi][3], bH[nj][0], bH[nj][1]);
                mma_bf16(c, aH[mi][0], aH[mi][1], aH[mi][2], aH[mi][3], bL[nj][0], bL[nj][1]);
                mma_bf16(c, aL[mi][0], aL[mi][1], aL[mi][2], aL[mi][3], bH[nj][0], bH[nj][1]);
            }
    }
}

// ---------------------------------------------------------------------------
// GEMM1: grid (B/128, 256/128, SPLITS), block 512; K-chunk 512 (8 steps)
// ---------------------------------------------------------------------------
__global__ __launch_bounds__(512) void gemm1_hmma(int Brows) {
    extern __shared__ char sm[];
    const uint32_t sb = smem_u32(sm);
    const int tid = threadIdx.x, wid = tid >> 5, lane = tid & 31;
    const int wm = wid & 3, wn = wid >> 2;
    const int mt = blockIdx.x, nt = blockIdx.y, sp = blockIdx.z;
    const int k0 = sp * (N_GRID / SPLITS);
    const int NS = (N_GRID / SPLITS) / 64;

    float acc[2][4][4];
#pragma unroll
    for (int a = 0; a < 2; a++)
#pragma unroll
        for (int b = 0; b < 4; b++)
#pragma unroll
            for (int c = 0; c < 4; c++) acc[a][b][c] = 0.0f;

    const __nv_bfloat16* aHsrc = g_rho_hi + (size_t)(mt * 128) * N_GRID + k0;
    const __nv_bfloat16* aLsrc = g_rho_lo + (size_t)(mt * 128) * N_GRID + k0;
    const __nv_bfloat16* bHsrc = g_Cs_hi  + (size_t)(nt * 128) * N_GRID + k0;
    const __nv_bfloat16* bLsrc = g_Cs_lo  + (size_t)(nt * 128) * N_GRID + k0;

    {
        tile_async(sb,         aHsrc, N_GRID, tid);
        tile_async(sb + SM_AL, aLsrc, N_GRID, tid);
        tile_async(sb + SM_BH, bHsrc, N_GRID, tid);
        tile_async(sb + SM_BL, bLsrc, N_GRID, tid);
        cp_commit();
    }
    for (int s = 0; s < NS; s++) {
        if (s + 1 < NS) {
            uint32_t st = sb + ((s + 1) & 1) * STG;
            int ko = (s + 1) * 64;
            tile_async(st,         aHsrc + ko, N_GRID, tid);
            tile_async(st + SM_AL, aLsrc + ko, N_GRID, tid);
            tile_async(st + SM_BH, bHsrc + ko, N_GRID, tid);
            tile_async(st + SM_BL, bLsrc + ko, N_GRID, tid);
            cp_commit();
            cp_wait<1>();
        } else {
            cp_wait<0>();
        }
        __syncthreads();
        compute_step(sb + (s & 1) * STG, wm, wn, lane, acc);
        __syncthreads();
    }

    const int g = lane >> 2, tig = lane & 3;
    const int mbase = mt * 128 + wm * 32;
    const int nbase = nt * 128 + wn * 32;
#pragma unroll
    for (int mi = 0; mi < 2; mi++)
#pragma unroll
        for (int nj = 0; nj < 4; nj++) {
            int row = mbase + mi * 16 + g;
            int col = nbase + nj * 8 + tig * 2;
            float* p0 = g_part + ((size_t)sp * Brows + row) * R_MS + col;
            *(float2*)p0              = make_float2(acc[mi][nj][0], acc[mi][nj][1]);
            *(float2*)(p0 + 8 * R_MS) = make_float2(acc[mi][nj][2], acc[mi][nj][3]);
        }
}

__global__ void reduce_lam_kernel(const float* __restrict__ ms, int Brows) {
    int idx = blockIdx.x * blockDim.x + threadIdx.x;
    int j = idx & (R_MS - 1);
    float sum = 0.0f;
#pragma unroll
    for (int s = 0; s < SPLITS; s++)
        sum += g_part[(size_t)s * Brows * R_MS + idx];
    float v = ms[j] * sum;
    __nv_bfloat16 h, l;
    split2(v, h, l);
    g_A_hi[idx] = h;
    g_A_lo[idx] = l;
}

// ---------------------------------------------------------------------------
// GEMM2: grid (B/128, 4096/128), block 512; K = 256 (4 steps)
// ---------------------------------------------------------------------------
__global__ __launch_bounds__(512) void gemm2_hmma(float* __restrict__ phi) {
    extern __shared__ char sm[];
    const uint32_t sb = smem_u32(sm);
    const int tid = threadIdx.x, wid = tid >> 5, lane = tid & 31;
    const int wm = wid & 3, wn = wid >> 2;
    const int mt = blockIdx.x, nt = blockIdx.y;
    const int NS = R_MS / 64;

    float acc[2][4][4];
#pragma unroll
    for (int a = 0; a < 2; a++)
#pragma unroll
        for (int b = 0; b < 4; b++)
#pragma unroll
            for (int c = 0; c < 4; c++) acc[a][b][c] = 0.0f;

    const __nv_bfloat16* aHsrc = g_A_hi   + (size_t)(mt * 128) * R_MS;
    const __nv_bfloat16* aLsrc = g_A_lo   + (size_t)(mt * 128) * R_MS;
    const __nv_bfloat16* bHsrc = g_CsT_hi + (size_t)(nt * 128) * R_MS;
    const __nv_bfloat16* bLsrc = g_CsT_lo + (size_t)(nt * 128) * R_MS;

    {
        tile_async(sb,         aHsrc, R_MS, tid);
        tile_async(sb + SM_AL, aLsrc, R_MS, tid);
        tile_async(sb + SM_BH, bHsrc, R_MS, tid);
        tile_async(sb + SM_BL, bLsrc, R_MS, tid);
        cp_commit();
    }
    for (int s = 0; s < NS; s++) {
        if (s + 1 < NS) {
            uint32_t st = sb + ((s + 1) & 1) * STG;
            int ko = (s + 1) * 64;
            tile_async(st,         aHsrc + ko, R_MS, tid);
            tile_async(st + SM_AL, aLsrc + ko, R_MS, tid);
            tile_async(st + SM_BH, bHsrc + ko, R_MS, tid);
            tile_async(st + SM_BL, bLsrc + ko, R_MS, tid);
            cp_commit();
            cp_wait<1>();
        } else {
            cp_wait<0>();
        }
        __syncthreads();
        compute_step(sb + (s & 1) * STG, wm, wn, lane, acc);
        __syncthreads();
    }

    const int g = lane >> 2, tig = lane & 3;
    const int mbase = mt * 128 + wm * 32;
    const int nbase = nt * 128 + wn * 32;
#pragma unroll
    for (int mi = 0; mi < 2; mi++)
#pragma unroll
        for (int nj = 0; nj < 4; nj++) {
            int r = mbase + mi * 16 + g;
            int c = nbase + nj * 8 + tig * 2;
            float* p0 = phi + (size_t)r * N_GRID + c;
            *(float2*)p0                = make_float2(acc[mi][nj][0], acc[mi][nj][1]);
            *(float2*)(p0 + 8 * N_GRID) = make_float2(acc[mi][nj][2], acc[mi][nj][3]);
        }
}

// ---------------------------------------------------------------------------
extern "C" void kernel_launch(void* const* d_in, const int* in_sizes, int n_in,
                              void* d_out, int out_size) {
    const float* rho = (const float*)d_in[0];
    const float* ms  = (const float*)d_in[1];
    float* phi = (float*)d_out;
    const int Brows = in_sizes[0] / N_GRID;

    cudaFuncSetAttribute(gemm1_hmma, cudaFuncAttributeMaxDynamicSharedMemorySize, SMEM_BYTES);
    cudaFuncSetAttribute(gemm2_hmma, cudaFuncAttributeMaxDynamicSharedMemorySize, SMEM_BYTES);

    prep_kernel<<<12288, 256>>>(rho);

    dim3 g1(Brows / 128, R_MS / 128, SPLITS);
    gemm1_hmma<<<g1, 512, SMEM_BYTES>>>(Brows);

    reduce_lam_kernel<<<(Brows * R_MS) / 256, 256>>>(ms, Brows);

    dim3 g2(Brows / 128, N_GRID / 128);
    gemm2_hmma<<<g2, 512, SMEM_BYTES>>>(phi);
}

// round 6
// speedup vs baseline: 3.2671x; 1.3363x over previous
#include <cuda_runtime.h>
#include <cuda_bf16.h>
#include <math.h>
#include <stdint.h>

#define N_GRID 4096
#define NH     2048
#define R_MS   256
#define SPLITS 8
#define MAXB   1024

// ---------------- device scratch ----------------
__device__ __nv_bfloat16 g_uP_hi[MAXB * NH];        // u+ = rho[n'] + rho[4095-n']
__device__ __nv_bfloat16 g_uP_lo[MAXB * NH];
__device__ __nv_bfloat16 g_uM_hi[MAXB * NH];        // u-
__device__ __nv_bfloat16 g_uM_lo[MAXB * NH];
__device__ __nv_bfloat16 g_CsF_hi[2 * 128 * NH];    // folded Cs [g][k'][n']
__device__ __nv_bfloat16 g_CsF_lo[2 * 128 * NH];
__device__ __nv_bfloat16 g_CsT_hi[2 * NH * 128];    // folded Cs [g][n'][k']
__device__ __nv_bfloat16 g_CsT_lo[2 * NH * 128];
__device__ float         g_part  [16 * MAXB * 128]; // [g*8+sp][b][k']
__device__ __nv_bfloat16 g_Ae_hi[MAXB * 128];       // lam-scaled even coeffs
__device__ __nv_bfloat16 g_Ae_lo[MAXB * 128];
__device__ __nv_bfloat16 g_Ao_hi[MAXB * 128];
__device__ __nv_bfloat16 g_Ao_lo[MAXB * 128];

// ---------------- helpers ----------------
__device__ __forceinline__ uint32_t smem_u32(const void* p) {
    uint32_t a;
    asm("{ .reg .u64 t; cvta.to.shared.u64 t, %1; cvt.u32.u64 %0, t; }" : "=r"(a) : "l"(p));
    return a;
}
__device__ __forceinline__ uint32_t swz(uint32_t off) { return off ^ ((off >> 3) & 0x70); }

__device__ __forceinline__ void cp16(uint32_t dst, const void* src) {
    asm volatile("cp.async.cg.shared.global [%0], [%1], 16;" :: "r"(dst), "l"(src));
}
__device__ __forceinline__ void cp_commit() {
    asm volatile("cp.async.commit_group;" ::: "memory");
}
template <int N>
__device__ __forceinline__ void cp_wait() {
    asm volatile("cp.async.wait_group %0;" :: "n"(N) : "memory");
}

__device__ __forceinline__ void ldsm_x4(uint32_t& r0, uint32_t& r1, uint32_t& r2, uint32_t& r3,
                                        uint32_t addr) {
    asm volatile("ldmatrix.sync.aligned.m8n8.x4.shared.b16 {%0,%1,%2,%3}, [%4];"
                 : "=r"(r0), "=r"(r1), "=r"(r2), "=r"(r3) : "r"(addr));
}
__device__ __forceinline__ void ldsm_x2(uint32_t& r0, uint32_t& r1, uint32_t addr) {
    asm volatile("ldmatrix.sync.aligned.m8n8.x2.shared.b16 {%0,%1}, [%2];"
                 : "=r"(r0), "=r"(r1) : "r"(addr));
}
__device__ __forceinline__ void mma_bf16(float* c, uint32_t a0, uint32_t a1, uint32_t a2,
                                         uint32_t a3, uint32_t b0, uint32_t b1) {
    asm volatile("mma.sync.aligned.m16n8k16.row.col.f32.bf16.bf16.f32 "
                 "{%0,%1,%2,%3}, {%4,%5,%6,%7}, {%8,%9}, {%0,%1,%2,%3};"
                 : "+f"(c[0]), "+f"(c[1]), "+f"(c[2]), "+f"(c[3])
                 : "r"(a0), "r"(a1), "r"(a2), "r"(a3), "r"(b0), "r"(b1));
}

__device__ __forceinline__ void split2(float v, __nv_bfloat16& h, __nv_bfloat16& l) {
    h = __float2bfloat16(v);
    l = __float2bfloat16(v - __bfloat162float(h));
}

// ---------------------------------------------------------------------------
__device__ __forceinline__ float cos_acc(float x) {
    const float INV_PIO2 = 0.6366197723675814f;
    float qf = rintf(x * INV_PIO2);
    int   iq = (int)qf;
    const float HI = 1.57079637050628662109375f;
    const float MD = -4.3711388286737929e-08f;
    const float LO = -1.7151245100059657e-15f;
    float r = fmaf(-qf, HI, x);
    r = fmaf(-qf, MD, r);
    r = fmaf(-qf, LO, r);
    float r2 = r * r;
    float pc = fmaf(r2,  2.4390448796e-05f, -1.3886763775e-03f);
    pc = fmaf(r2, pc,  4.1666623323e-02f);
    pc = fmaf(r2, pc, -4.9999999725e-01f);
    pc = fmaf(r2, pc,  1.0f);
    float ps = fmaf(r2,  2.7183114939e-06f, -1.9839334836e-04f);
    ps = fmaf(r2, ps,  8.3333293859e-03f);
    ps = fmaf(r2, ps, -1.6666666642e-01f);
    ps = r * fmaf(r2, ps, 1.0f);
    int n = iq & 3;
    float v = (n & 1) ? ps : pc;
    if (n == 1 || n == 2) v = -v;
    return v;
}

__device__ __forceinline__ float cs_val(int n, int k) {
    const float PI_F = 3.1415927410125732421875f;
    float t1 = PI_F * (float)(2 * n + 1);
    float theta = (t1 * (float)k) * (1.0f / 8192.0f);
    const float SCALE = 0.02209708691f;               // sqrt(2/4096)
    return SCALE * cos_acc(theta);
}

// ---------------------------------------------------------------------------
// prep: [0,2048) fold rho -> u+/u- hi/lo ; [2048,4096) CsF ; [4096,6144) CsT
// ---------------------------------------------------------------------------
__global__ void prep_kernel(const float* __restrict__ rho) {
    int bx = blockIdx.x;
    if (bx < 2048) {
        int t = bx * 256 + threadIdx.x;      // 0..512K-1, 4 n' each
        int b = t >> 9;
        int np = (t & 511) * 4;
        float4 f = *(const float4*)(rho + (size_t)b * N_GRID + np);
        float4 r = *(const float4*)(rho + (size_t)b * N_GRID + (4092 - np));
        float up[4] = {f.x + r.w, f.y + r.z, f.z + r.y, f.w + r.x};
        float um[4] = {f.x - r.w, f.y - r.z, f.z - r.y, f.w - r.x};
        __nv_bfloat16 ph[4], pl[4], mh[4], ml[4];
#pragma unroll
        for (int j = 0; j < 4; j++) { split2(up[j], ph[j], pl[j]); split2(um[j], mh[j], ml[j]); }
        ((uint2*)g_uP_hi)[t] = *(uint2*)ph;
        ((uint2*)g_uP_lo)[t] = *(uint2*)pl;
        ((uint2*)g_uM_hi)[t] = *(uint2*)mh;
        ((uint2*)g_uM_lo)[t] = *(uint2*)ml;
    } else if (bx < 4096) {
        int t = (bx - 2048) * 256 + threadIdx.x;   // [g][k'][n']
        int g = t >> 18;
        int rem = t & 0x3FFFF;
        int kp = rem >> 11, np = rem & (NH - 1);
        int k = g ? (2 * kp + 1) : (2 * kp + 2);
        float c1 = cs_val(np, k), c2 = cs_val(4095 - np, k);
        float v = 0.5f * (g ? (c1 - c2) : (c1 + c2));
        __nv_bfloat16 h, l;
        split2(v, h, l);
        g_CsF_hi[t] = h; g_CsF_lo[t] = l;
    } else {
        int t = (bx - 4096) * 256 + threadIdx.x;   // [g][n'][k']
        int g = t >> 18;
        int rem = t & 0x3FFFF;
        int np = rem >> 7, kp = rem & 127;
        int k = g ? (2 * kp + 1) : (2 * kp + 2);
        float c1 = cs_val(np, k), c2 = cs_val(4095 - np, k);
        float v = 0.5f * (g ? (c1 - c2) : (c1 + c2));
        __nv_bfloat16 h, l;
        split2(v, h, l);
        g_CsT_hi[t] = h; g_CsT_lo[t] = l;
    }
}

// ---------------------------------------------------------------------------
// async tile fills (512 threads)
// ---------------------------------------------------------------------------
__device__ __forceinline__ void tile_async(uint32_t dst, const __nv_bfloat16* src,
                                           int stride, int tid) {          // 128x64
    const int row = tid >> 2;
    const int c0 = tid & 3;
    const char* s = (const char*)(src + (size_t)row * stride);
#pragma unroll
    for (int i = 0; i < 2; i++) {
        int ch = c0 + i * 4;
        cp16(dst + swz((uint32_t)row * 128 + ch * 16), s + ch * 16);
    }
}
__device__ __forceinline__ void tile_async64(uint32_t dst, const __nv_bfloat16* src,
                                             int stride, int tid) {        // 64x64
    const int row = tid >> 3;
    const int ch = tid & 7;
    cp16(dst + swz((uint32_t)row * 128 + ch * 16), (const char*)(src + (size_t)row * stride) + ch * 16);
}

// one 64-wide K step; warp tile 32x32; A at aB (+ALO lo), B at bB (+BLO lo)
template <int ALO, int BLO>
__device__ __forceinline__ void compute_step(uint32_t aB, uint32_t bB, int wm, int wn,
                                             int lane, float acc[2][4][4]) {
    const uint32_t aRow = (uint32_t)(wm * 32 + (lane & 15)) * 128 + ((lane >> 4) << 4);
    const uint32_t bRow = (uint32_t)(wn * 32 + (lane & 7)) * 128 + (((lane >> 3) & 1) << 4);
#pragma unroll
    for (int k16 = 0; k16 < 4; k16++) {
        const uint32_t kb = k16 * 32;
        uint32_t aH[2][4], aL[2][4];
#pragma unroll
        for (int mi = 0; mi < 2; mi++) {
            uint32_t off = swz(aRow + mi * 16 * 128 + kb);
            ldsm_x4(aH[mi][0], aH[mi][1], aH[mi][2], aH[mi][3], aB + off);
            ldsm_x4(aL[mi][0], aL[mi][1], aL[mi][2], aL[mi][3], aB + ALO + off);
        }
        uint32_t bH[4][2], bL[4][2];
#pragma unroll
        for (int nj = 0; nj < 4; nj++) {
            uint32_t off = swz(bRow + nj * 8 * 128 + kb);
            ldsm_x2(bH[nj][0], bH[nj][1], bB + off);
            ldsm_x2(bL[nj][0], bL[nj][1], bB + BLO + off);
        }
#pragma unroll
        for (int mi = 0; mi < 2; mi++)
#pragma unroll
            for (int nj = 0; nj < 4; nj++) {
                float* c = acc[mi][nj];
                mma_bf16(c, aH[mi][0], aH[mi][1], aH[mi][2], aH[mi][3], bH[nj][0], bH[nj][1]);
                mma_bf16(c, aH[mi][0], aH[mi][1], aH[mi][2], aH[mi][3], bL[nj][0], bL[nj][1]);
                mma_bf16(c, aL[mi][0], aL[mi][1], aL[mi][2], aL[mi][3], bH[nj][0], bH[nj][1]);
            }
    }
}

// ---------------------------------------------------------------------------
// GEMM1: part[g*8+sp][b][k'] = sum_{n' chunk} u_g[b][n'] * CsF[g][k'][n']
// grid (B/128, 2, SPLITS), block 512; K-chunk 256 (4 steps of 64)
// smem stage 64KB: AH 0, AL 16K, BH 32K, BL 48K
// ---------------------------------------------------------------------------
#define STG1 65536
#define SMEM1_BYTES (2 * STG1)

__global__ __launch_bounds__(512) void gemm1_hmma(int Brows) {
    extern __shared__ char sm[];
    const uint32_t sb = smem_u32(sm);
    const int tid = threadIdx.x, wid = tid >> 5, lane = tid & 31;
    const int wm = wid & 3, wn = wid >> 2;
    const int mt = blockIdx.x, grp = blockIdx.y, sp = blockIdx.z;
    const int k0 = sp * (NH / SPLITS);               // 256-chunk
    const int NS = (NH / SPLITS) / 64;               // 4

    float acc[2][4][4];
#pragma unroll
    for (int a = 0; a < 2; a++)
#pragma unroll
        for (int b = 0; b < 4; b++)
#pragma unroll
            for (int c = 0; c < 4; c++) acc[a][b][c] = 0.0f;

    const __nv_bfloat16* aHsrc = (grp ? g_uM_hi : g_uP_hi) + (size_t)(mt * 128) * NH + k0;
    const __nv_bfloat16* aLsrc = (grp ? g_uM_lo : g_uP_lo) + (size_t)(mt * 128) * NH + k0;
    const __nv_bfloat16* bHsrc = g_CsF_hi + (size_t)grp * 128 * NH + k0;
    const __nv_bfloat16* bLsrc = g_CsF_lo + (size_t)grp * 128 * NH + k0;

    {
        tile_async(sb,         aHsrc, NH, tid);
        tile_async(sb + 16384, aLsrc, NH, tid);
        tile_async(sb + 32768, bHsrc, NH, tid);
        tile_async(sb + 49152, bLsrc, NH, tid);
        cp_commit();
    }
    for (int s = 0; s < NS; s++) {
        if (s + 1 < NS) {
            uint32_t st = sb + ((s + 1) & 1) * STG1;
            int ko = (s + 1) * 64;
            tile_async(st,         aHsrc + ko, NH, tid);
            tile_async(st + 16384, aLsrc + ko, NH, tid);
            tile_async(st + 32768, bHsrc + ko, NH, tid);
            tile_async(st + 49152, bLsrc + ko, NH, tid);
            cp_commit();
            cp_wait<1>();
        } else {
            cp_wait<0>();
        }
        __syncthreads();
        uint32_t st = sb + (s & 1) * STG1;
        compute_step<16384, 16384>(st, st + 32768, wm, wn, lane, acc);
        __syncthreads();
    }

    const int g = lane >> 2, tig = lane & 3;
    const int mbase = mt * 128 + wm * 32;
    const int nbase = wn * 32;
#pragma unroll
    for (int mi = 0; mi < 2; mi++)
#pragma unroll
        for (int nj = 0; nj < 4; nj++) {
            int row = mbase + mi * 16 + g;
            int col = nbase + nj * 8 + tig * 2;
            float* p0 = g_part + ((size_t)(grp * SPLITS + sp) * Brows + row) * 128 + col;
            *(float2*)p0            = make_float2(acc[mi][nj][0], acc[mi][nj][1]);
            *(float2*)(p0 + 8 * 128) = make_float2(acc[mi][nj][2], acc[mi][nj][3]);
        }
}

// reduce splits + lam scale -> bf16 hi/lo coefficients (per group)
__global__ void reduce_lam_kernel(const float* __restrict__ ms, int Brows) {
    int g = blockIdx.y;
    int idx = blockIdx.x * blockDim.x + threadIdx.x;   // b*128 + k'
    int kp = idx & 127;
    float sum = 0.0f;
#pragma unroll
    for (int s = 0; s < SPLITS; s++)
        sum += g_part[(size_t)(g * SPLITS + s) * Brows * 128 + idx];
    float v = ms[g ? (2 * kp) : (2 * kp + 1)] * sum;
    __nv_bfloat16 h, l;
    split2(v, h, l);
    if (g) { g_Ao_hi[idx] = h; g_Ao_lo[idx] = l; }
    else   { g_Ae_hi[idx] = h; g_Ae_lo[idx] = l; }
}

// ---------------------------------------------------------------------------
// GEMM2: e = A_e @ CsTE^T, o = A_o @ CsTO^T over 64 n'-cols; phi[n']=e+o,
// phi[4095-n']=e-o.  grid (B/128, NH/64), block 512.
// Warps wn<2 compute e, wn>=2 compute o (warp tile 32x32 on the 128x64 tile).
// smem stage 96KB: AeH 0, AeL 16K, AoH 32K, AoL 48K, BeH 64K, BeL 72K,
//                  BoH 80K, BoL 88K.  Epilogue reuses 64KB for f32 exchange.
// ---------------------------------------------------------------------------
#define STG2 98304
#define SMEM2_BYTES (2 * STG2)

__global__ __launch_bounds__(512) void gemm2_hmma(float* __restrict__ phi) {
    extern __shared__ char sm[];
    const uint32_t sb = smem_u32(sm);
    const int tid = threadIdx.x, wid = tid >> 5, lane = tid & 31;
    const int wm = wid & 3, wn = wid >> 2;
    const bool isE = (wn < 2);
    const int wnl = wn & 1;
    const int mt = blockIdx.x, nt = blockIdx.y;

    float acc[2][4][4];
#pragma unroll
    for (int a = 0; a < 2; a++)
#pragma unroll
        for (int b = 0; b < 4; b++)
#pragma unroll
            for (int c = 0; c < 4; c++) acc[a][b][c] = 0.0f;

    const size_t aoff = (size_t)(mt * 128) * 128;
    const size_t boffE = (size_t)nt * 64 * 128;
    const size_t boffO = (size_t)NH * 128 + boffE;

#define FILL2(stage, ko)                                                     \
    do {                                                                     \
        uint32_t st_ = (stage);                                              \
        tile_async(st_,          g_Ae_hi + aoff + (ko), 128, tid);           \
        tile_async(st_ + 16384,  g_Ae_lo + aoff + (ko), 128, tid);           \
        tile_async(st_ + 32768,  g_Ao_hi + aoff + (ko), 128, tid);           \
        tile_async(st_ + 49152,  g_Ao_lo + aoff + (ko), 128, tid);           \
        tile_async64(st_ + 65536, g_CsT_hi + boffE + (ko), 128, tid);        \
        tile_async64(st_ + 73728, g_CsT_lo + boffE + (ko), 128, tid);        \
        tile_async64(st_ + 81920, g_CsT_hi + boffO + (ko), 128, tid);        \
        tile_async64(st_ + 90112, g_CsT_lo + boffO + (ko), 128, tid);        \
        cp_commit();                                                         \
    } while (0)

    FILL2(sb, 0);
    for (int s = 0; s < 2; s++) {
        if (s == 0) {
            FILL2(sb + STG2, 64);
            cp_wait<1>();
        } else {
            cp_wait<0>();
        }
        __syncthreads();
        uint32_t st = sb + (s & 1) * STG2;
        uint32_t aB = st + (isE ? 0u : 32768u);
        uint32_t bB = st + (isE ? 65536u : 81920u);
        compute_step<16384, 8192>(aB, bB, wm, wnl, lane, acc);
        __syncthreads();
    }

    // exchange e/o through smem (f32 128x64 each)
    {
        char* base = sm + (isE ? 0 : 32768);
        const int g = lane >> 2, tig = lane & 3;
#pragma unroll
        for (int mi = 0; mi < 2; mi++)
#pragma unroll
            for (int nj = 0; nj < 4; nj++) {
                int lrow = wm * 32 + mi * 16 + g;
                int lcol = wnl * 32 + nj * 8 + tig * 2;
                *(float2*)(base + ((size_t)lrow * 64 + lcol) * 4)
                    = make_float2(acc[mi][nj][0], acc[mi][nj][1]);
                *(float2*)(base + ((size_t)(lrow + 8) * 64 + lcol) * 4)
                    = make_float2(acc[mi][nj][2], acc[mi][nj][3]);
            }
    }
    __syncthreads();

    // assemble phi forward + backward halves
    {
        const int lr = tid >> 2;
        const int cg = (tid & 3) * 16;
        const float* pe = (const float*)sm + (size_t)lr * 64 + cg;
        const float* po = (const float*)(sm + 32768) + (size_t)lr * 64 + cg;
        float* rowp = phi + (size_t)(mt * 128 + lr) * N_GRID;
        const int n0 = nt * 64 + cg;
#pragma unroll
        for (int i = 0; i < 4; i++) {
            float4 e = *(const float4*)(pe + i * 4);
            float4 o = *(const float4*)(po + i * 4);
            int c = n0 + i * 4;
            *(float4*)(rowp + c) = make_float4(e.x + o.x, e.y + o.y, e.z + o.z, e.w + o.w);
            *(float4*)(rowp + (4092 - c)) = make_float4(e.w - o.w, e.z - o.z, e.y - o.y, e.x - o.x);
        }
    }
}

// ---------------------------------------------------------------------------
extern "C" void kernel_launch(void* const* d_in, const int* in_sizes, int n_in,
                              void* d_out, int out_size) {
    const float* rho = (const float*)d_in[0];
    const float* ms  = (const float*)d_in[1];
    float* phi = (float*)d_out;
    const int Brows = in_sizes[0] / N_GRID;     // 1024

    cudaFuncSetAttribute(gemm1_hmma, cudaFuncAttributeMaxDynamicSharedMemorySize, SMEM1_BYTES);
    cudaFuncSetAttribute(gemm2_hmma, cudaFuncAttributeMaxDynamicSharedMemorySize, SMEM2_BYTES);

    prep_kernel<<<6144, 256>>>(rho);

    dim3 g1(Brows / 128, 2, SPLITS);
    gemm1_hmma<<<g1, 512, SMEM1_BYTES>>>(Brows);

    dim3 gr((Brows * 128) / 256, 2);
    reduce_lam_kernel<<<gr, 256>>>(ms, Brows);

    dim3 g2(Brows / 128, NH / 64);
    gemm2_hmma<<<g2, 512, SMEM2_BYTES>>>(phi);
}

// round 7
// speedup vs baseline: 3.4312x; 1.0502x over previous
#include <cuda_runtime.h>
#include <cuda_bf16.h>
#include <math.h>
#include <stdint.h>

#define N_GRID 4096
#define NH     2048
#define SPLITS 8
#define MAXB   1024

// ---------------- device scratch ----------------
__device__ __nv_bfloat16 g_uP_hi[MAXB * NH];
__device__ __nv_bfloat16 g_uP_lo[MAXB * NH];
__device__ __nv_bfloat16 g_uM_hi[MAXB * NH];
__device__ __nv_bfloat16 g_uM_lo[MAXB * NH];
__device__ __nv_bfloat16 g_CsF_hi[2 * 128 * NH];
__device__ __nv_bfloat16 g_CsF_lo[2 * 128 * NH];
__device__ __nv_bfloat16 g_CsT_hi[2 * NH * 128];
__device__ __nv_bfloat16 g_CsT_lo[2 * NH * 128];
__device__ float         g_part  [16 * MAXB * 128];
__device__ __nv_bfloat16 g_Ae_hi[MAXB * 128];
__device__ __nv_bfloat16 g_Ae_lo[MAXB * 128];
__device__ __nv_bfloat16 g_Ao_hi[MAXB * 128];
__device__ __nv_bfloat16 g_Ao_lo[MAXB * 128];

// ---------------- helpers ----------------
__device__ __forceinline__ uint32_t smem_u32(const void* p) {
    uint32_t a;
    asm("{ .reg .u64 t; cvta.to.shared.u64 t, %1; cvt.u32.u64 %0, t; }" : "=r"(a) : "l"(p));
    return a;
}
__device__ __forceinline__ uint32_t swz(uint32_t off) { return off ^ ((off >> 3) & 0x70); }

__device__ __forceinline__ void cp16(uint32_t dst, const void* src) {
    asm volatile("cp.async.cg.shared.global [%0], [%1], 16;" :: "r"(dst), "l"(src));
}
__device__ __forceinline__ void cp_commit() {
    asm volatile("cp.async.commit_group;" ::: "memory");
}
template <int N>
__device__ __forceinline__ void cp_wait() {
    asm volatile("cp.async.wait_group %0;" :: "n"(N) : "memory");
}

__device__ __forceinline__ void ldsm_x4(uint32_t& r0, uint32_t& r1, uint32_t& r2, uint32_t& r3,
                                        uint32_t addr) {
    asm volatile("ldmatrix.sync.aligned.m8n8.x4.shared.b16 {%0,%1,%2,%3}, [%4];"
                 : "=r"(r0), "=r"(r1), "=r"(r2), "=r"(r3) : "r"(addr));
}
__device__ __forceinline__ void ldsm_x2(uint32_t& r0, uint32_t& r1, uint32_t addr) {
    asm volatile("ldmatrix.sync.aligned.m8n8.x2.shared.b16 {%0,%1}, [%2];"
                 : "=r"(r0), "=r"(r1) : "r"(addr));
}
__device__ __forceinline__ void mma_bf16(float* c, uint32_t a0, uint32_t a1, uint32_t a2,
                                         uint32_t a3, uint32_t b0, uint32_t b1) {
    asm volatile("mma.sync.aligned.m16n8k16.row.col.f32.bf16.bf16.f32 "
                 "{%0,%1,%2,%3}, {%4,%5,%6,%7}, {%8,%9}, {%0,%1,%2,%3};"
                 : "+f"(c[0]), "+f"(c[1]), "+f"(c[2]), "+f"(c[3])
                 : "r"(a0), "r"(a1), "r"(a2), "r"(a3), "r"(b0), "r"(b1));
}

__device__ __forceinline__ void split2(float v, __nv_bfloat16& h, __nv_bfloat16& l) {
    h = __float2bfloat16(v);
    l = __float2bfloat16(v - __bfloat162float(h));
}

// ---------------------------------------------------------------------------
__device__ __forceinline__ float cos_acc(float x) {
    const float INV_PIO2 = 0.6366197723675814f;
    float qf = rintf(x * INV_PIO2);
    int   iq = (int)qf;
    const float HI = 1.57079637050628662109375f;
    const float MD = -4.3711388286737929e-08f;
    const float LO = -1.7151245100059657e-15f;
    float r = fmaf(-qf, HI, x);
    r = fmaf(-qf, MD, r);
    r = fmaf(-qf, LO, r);
    float r2 = r * r;
    float pc = fmaf(r2,  2.4390448796e-05f, -1.3886763775e-03f);
    pc = fmaf(r2, pc,  4.1666623323e-02f);
    pc = fmaf(r2, pc, -4.9999999725e-01f);
    pc = fmaf(r2, pc,  1.0f);
    float ps = fmaf(r2,  2.7183114939e-06f, -1.9839334836e-04f);
    ps = fmaf(r2, ps,  8.3333293859e-03f);
    ps = fmaf(r2, ps, -1.6666666642e-01f);
    ps = r * fmaf(r2, ps, 1.0f);
    int n = iq & 3;
    float v = (n & 1) ? ps : pc;
    if (n == 1 || n == 2) v = -v;
    return v;
}

__device__ __forceinline__ float cs_val(int n, int k) {
    const float PI_F = 3.1415927410125732421875f;
    float t1 = PI_F * (float)(2 * n + 1);
    float theta = (t1 * (float)k) * (1.0f / 8192.0f);
    const float SCALE = 0.02209708691f;
    return SCALE * cos_acc(theta);
}

// ---------------------------------------------------------------------------
__global__ void prep_kernel(const float* __restrict__ rho) {
    int bx = blockIdx.x;
    if (bx < 2048) {
        int t = bx * 256 + threadIdx.x;
        int b = t >> 9;
        int np = (t & 511) * 4;
        float4 f = *(const float4*)(rho + (size_t)b * N_GRID + np);
        float4 r = *(const float4*)(rho + (size_t)b * N_GRID + (4092 - np));
        float up[4] = {f.x + r.w, f.y + r.z, f.z + r.y, f.w + r.x};
        float um[4] = {f.x - r.w, f.y - r.z, f.z - r.y, f.w - r.x};
        __nv_bfloat16 ph[4], pl[4], mh[4], ml[4];
#pragma unroll
        for (int j = 0; j < 4; j++) { split2(up[j], ph[j], pl[j]); split2(um[j], mh[j], ml[j]); }
        ((uint2*)g_uP_hi)[t] = *(uint2*)ph;
        ((uint2*)g_uP_lo)[t] = *(uint2*)pl;
        ((uint2*)g_uM_hi)[t] = *(uint2*)mh;
        ((uint2*)g_uM_lo)[t] = *(uint2*)ml;
    } else if (bx < 4096) {
        int t = (bx - 2048) * 256 + threadIdx.x;
        int g = t >> 18;
        int rem = t & 0x3FFFF;
        int kp = rem >> 11, np = rem & (NH - 1);
        int k = g ? (2 * kp + 1) : (2 * kp + 2);
        float c1 = cs_val(np, k), c2 = cs_val(4095 - np, k);
        float v = 0.5f * (g ? (c1 - c2) : (c1 + c2));
        __nv_bfloat16 h, l;
        split2(v, h, l);
        g_CsF_hi[t] = h; g_CsF_lo[t] = l;
    } else {
        int t = (bx - 4096) * 256 + threadIdx.x;
        int g = t >> 18;
        int rem = t & 0x3FFFF;
        int np = rem >> 7, kp = rem & 127;
        int k = g ? (2 * kp + 1) : (2 * kp + 2);
        float c1 = cs_val(np, k), c2 = cs_val(4095 - np, k);
        float v = 0.5f * (g ? (c1 - c2) : (c1 + c2));
        __nv_bfloat16 h, l;
        split2(v, h, l);
        g_CsT_hi[t] = h; g_CsT_lo[t] = l;
    }
}

// ---------------------------------------------------------------------------
__device__ __forceinline__ void tile_async(uint32_t dst, const __nv_bfloat16* src,
                                           int stride, int tid) {          // 128x64
    const int row = tid >> 2;
    const int c0 = tid & 3;
    const char* s = (const char*)(src + (size_t)row * stride);
#pragma unroll
    for (int i = 0; i < 2; i++) {
        int ch = c0 + i * 4;
        cp16(dst + swz((uint32_t)row * 128 + ch * 16), s + ch * 16);
    }
}
__device__ __forceinline__ void tile_async64(uint32_t dst, const __nv_bfloat16* src,
                                             int stride, int tid) {        // 64x64
    const int row = tid >> 3;
    const int ch = tid & 7;
    cp16(dst + swz((uint32_t)row * 128 + ch * 16), (const char*)(src + (size_t)row * stride) + ch * 16);
}

// one 64-wide K step; warp tile 32x32
template <int ALO, int BLO>
__device__ __forceinline__ void compute_step(uint32_t aB, uint32_t bB, int wm, int wn,
                                             int lane, float acc[2][4][4]) {
    const uint32_t aRow = (uint32_t)(wm * 32 + (lane & 15)) * 128 + ((lane >> 4) << 4);
    const uint32_t bRow = (uint32_t)(wn * 32 + (lane & 7)) * 128 + (((lane >> 3) & 1) << 4);
#pragma unroll
    for (int k16 = 0; k16 < 4; k16++) {
        const uint32_t kb = k16 * 32;
        uint32_t aH[2][4], aL[2][4];
#pragma unroll
        for (int mi = 0; mi < 2; mi++) {
            uint32_t off = swz(aRow + mi * 16 * 128 + kb);
            ldsm_x4(aH[mi][0], aH[mi][1], aH[mi][2], aH[mi][3], aB + off);
            ldsm_x4(aL[mi][0], aL[mi][1], aL[mi][2], aL[mi][3], aB + ALO + off);
        }
        uint32_t bH[4][2], bL[4][2];
#pragma unroll
        for (int nj = 0; nj < 4; nj++) {
            uint32_t off = swz(bRow + nj * 8 * 128 + kb);
            ldsm_x2(bH[nj][0], bH[nj][1], bB + off);
            ldsm_x2(bL[nj][0], bL[nj][1], bB + BLO + off);
        }
#pragma unroll
        for (int mi = 0; mi < 2; mi++)
#pragma unroll
            for (int nj = 0; nj < 4; nj++) {
                float* c = acc[mi][nj];
                mma_bf16(c, aH[mi][0], aH[mi][1], aH[mi][2], aH[mi][3], bH[nj][0], bH[nj][1]);
                mma_bf16(c, aH[mi][0], aH[mi][1], aH[mi][2], aH[mi][3], bL[nj][0], bL[nj][1]);
                mma_bf16(c, aL[mi][0], aL[mi][1], aL[mi][2], aL[mi][3], bH[nj][0], bH[nj][1]);
            }
    }
}

// ---------------------------------------------------------------------------
// GEMM1 (unchanged from R6)
// ---------------------------------------------------------------------------
#define STG1 65536
#define SMEM1_BYTES (2 * STG1)

__global__ __launch_bounds__(512) void gemm1_hmma(int Brows) {
    extern __shared__ char sm[];
    const uint32_t sb = smem_u32(sm);
    const int tid = threadIdx.x, wid = tid >> 5, lane = tid & 31;
    const int wm = wid & 3, wn = wid >> 2;
    const int mt = blockIdx.x, grp = blockIdx.y, sp = blockIdx.z;
    const int k0 = sp * (NH / SPLITS);
    const int NS = (NH / SPLITS) / 64;

    float acc[2][4][4];
#pragma unroll
    for (int a = 0; a < 2; a++)
#pragma unroll
        for (int b = 0; b < 4; b++)
#pragma unroll
            for (int c = 0; c < 4; c++) acc[a][b][c] = 0.0f;

    const __nv_bfloat16* aHsrc = (grp ? g_uM_hi : g_uP_hi) + (size_t)(mt * 128) * NH + k0;
    const __nv_bfloat16* aLsrc = (grp ? g_uM_lo : g_uP_lo) + (size_t)(mt * 128) * NH + k0;
    const __nv_bfloat16* bHsrc = g_CsF_hi + (size_t)grp * 128 * NH + k0;
    const __nv_bfloat16* bLsrc = g_CsF_lo + (size_t)grp * 128 * NH + k0;

    {
        tile_async(sb,         aHsrc, NH, tid);
        tile_async(sb + 16384, aLsrc, NH, tid);
        tile_async(sb + 32768, bHsrc, NH, tid);
        tile_async(sb + 49152, bLsrc, NH, tid);
        cp_commit();
    }
    for (int s = 0; s < NS; s++) {
        if (s + 1 < NS) {
            uint32_t st = sb + ((s + 1) & 1) * STG1;
            int ko = (s + 1) * 64;
            tile_async(st,         aHsrc + ko, NH, tid);
            tile_async(st + 16384, aLsrc + ko, NH, tid);
            tile_async(st + 32768, bHsrc + ko, NH, tid);
            tile_async(st + 49152, bLsrc + ko, NH, tid);
            cp_commit();
            cp_wait<1>();
        } else {
            cp_wait<0>();
        }
        __syncthreads();
        uint32_t st = sb + (s & 1) * STG1;
        compute_step<16384, 16384>(st, st + 32768, wm, wn, lane, acc);
        __syncthreads();
    }

    const int g = lane >> 2, tig = lane & 3;
    const int mbase = mt * 128 + wm * 32;
    const int nbase = wn * 32;
#pragma unroll
    for (int mi = 0; mi < 2; mi++)
#pragma unroll
        for (int nj = 0; nj < 4; nj++) {
            int row = mbase + mi * 16 + g;
            int col = nbase + nj * 8 + tig * 2;
            float* p0 = g_part + ((size_t)(grp * SPLITS + sp) * Brows + row) * 128 + col;
            *(float2*)p0             = make_float2(acc[mi][nj][0], acc[mi][nj][1]);
            *(float2*)(p0 + 8 * 128) = make_float2(acc[mi][nj][2], acc[mi][nj][3]);
        }
}

__global__ void reduce_lam_kernel(const float* __restrict__ ms, int Brows) {
    int g = blockIdx.y;
    int idx = blockIdx.x * blockDim.x + threadIdx.x;
    int kp = idx & 127;
    float sum = 0.0f;
#pragma unroll
    for (int s = 0; s < SPLITS; s++)
        sum += g_part[(size_t)(g * SPLITS + s) * Brows * 128 + idx];
    float v = ms[g ? (2 * kp) : (2 * kp + 1)] * sum;
    __nv_bfloat16 h, l;
    split2(v, h, l);
    if (g) { g_Ao_hi[idx] = h; g_Ao_lo[idx] = l; }
    else   { g_Ae_hi[idx] = h; g_Ae_lo[idx] = l; }
}

// ---------------------------------------------------------------------------
// GEMM2 v2: grid (B/128, NH/128) = 128 CTAs, block 512.
// smem 192KB: A resident 128KB (AeH 0, AeL 32K, AoH 64K, AoL 96K; kc*16K inside),
// B ring 2x32KB @128K (BeH 0, BeL 8K, BoH 16K, BoL 24K within buf).
// Per n'-half (64 cols): 2 k-chunks accumulate; epilogue reuses dead B buf as
// e/o exchange scratch (2 sub-passes of 32 cols).
// ---------------------------------------------------------------------------
#define B_BASE 131072
#define SMEM2_BYTES 196608

__device__ __forceinline__ void fill_B(uint32_t sb, int buf, int nt, int h, int kc, int tid) {
    size_t be = ((size_t)(nt * 128 + h * 64)) * 128 + kc * 64;
    size_t bo = (size_t)NH * 128 + be;
    uint32_t bb = sb + B_BASE + buf * 32768;
    tile_async64(bb,         g_CsT_hi + be, 128, tid);
    tile_async64(bb + 8192,  g_CsT_lo + be, 128, tid);
    tile_async64(bb + 16384, g_CsT_hi + bo, 128, tid);
    tile_async64(bb + 24576, g_CsT_lo + bo, 128, tid);
    cp_commit();
}

__global__ __launch_bounds__(512) void gemm2_hmma(float* __restrict__ phi) {
    extern __shared__ char sm[];
    const uint32_t sb = smem_u32(sm);
    const int tid = threadIdx.x, wid = tid >> 5, lane = tid & 31;
    const int wm = wid & 3, wn = wid >> 2;
    const bool isE = (wn < 2);
    const int wnl = wn & 1;
    const int mt = blockIdx.x, nt = blockIdx.y;

    // A resident fill (8 tiles = 128KB)
    {
        const size_t aoff = (size_t)(mt * 128) * 128;
#pragma unroll
        for (int kc = 0; kc < 2; kc++) {
            tile_async(sb + kc * 16384,          g_Ae_hi + aoff + kc * 64, 128, tid);
            tile_async(sb + 32768 + kc * 16384,  g_Ae_lo + aoff + kc * 64, 128, tid);
            tile_async(sb + 65536 + kc * 16384,  g_Ao_hi + aoff + kc * 64, 128, tid);
            tile_async(sb + 98304 + kc * 16384,  g_Ao_lo + aoff + kc * 64, 128, tid);
        }
    }
    fill_B(sb, 0, nt, 0, 0, tid);   // group 0 (A + B h0kc0)
    fill_B(sb, 1, nt, 0, 1, tid);   // group 1

    float acc[2][4][4];

    for (int h = 0; h < 2; h++) {
#pragma unroll
        for (int a = 0; a < 2; a++)
#pragma unroll
            for (int b = 0; b < 4; b++)
#pragma unroll
                for (int c = 0; c < 4; c++) acc[a][b][c] = 0.0f;

        // kc = 0 on buf 0
        if (h == 0) cp_wait<1>(); else cp_wait<1>();
        __syncthreads();
        {
            uint32_t aB = sb + (isE ? 0u : 65536u);               // kc0
            uint32_t bB = sb + B_BASE + (isE ? 0u : 16384u);      // buf0
            compute_step<32768, 8192>(aB, bB, wm, wnl, lane, acc);
        }
        __syncthreads();
        if (h == 0) fill_B(sb, 0, nt, 1, 0, tid);                 // prefetch h1kc0 -> buf0

        // kc = 1 on buf 1
        if (h == 0) cp_wait<1>(); else cp_wait<0>();
        __syncthreads();
        {
            uint32_t aB = sb + 16384u + (isE ? 0u : 65536u);      // kc1
            uint32_t bB = sb + B_BASE + 32768u + (isE ? 0u : 16384u);
            compute_step<32768, 8192>(aB, bB, wm, wnl, lane, acc);
        }

        // epilogue for this half; X = dead B buffer (buf1 for h0, buf0 for h1)
        uint32_t xoff = B_BASE + (h == 0 ? 32768u : 0u);
        const int g = lane >> 2, tig = lane & 3;
#pragma unroll
        for (int p = 0; p < 2; p++) {
            __syncthreads();            // all reads of B buf done / prev subpass done
            if (wnl == p) {
                char* base = sm + xoff + (isE ? 0 : 16384);
#pragma unroll
                for (int mi = 0; mi < 2; mi++)
#pragma unroll
                    for (int nj = 0; nj < 4; nj++) {
                        int lrow = wm * 32 + mi * 16 + g;
                        int lcol = nj * 8 + tig * 2;
                        *(float2*)(base + ((size_t)lrow * 32 + lcol) * 4)
                            = make_float2(acc[mi][nj][0], acc[mi][nj][1]);
                        *(float2*)(base + ((size_t)(lrow + 8) * 32 + lcol) * 4)
                            = make_float2(acc[mi][nj][2], acc[mi][nj][3]);
                    }
            }
            __syncthreads();
            const int lr = tid >> 2;
            const int cg = (tid & 3) * 8;
            const float* pe = (const float*)(sm + xoff) + (size_t)lr * 32 + cg;
            const float* po = (const float*)(sm + xoff + 16384) + (size_t)lr * 32 + cg;
            float* rowp = phi + (size_t)(mt * 128 + lr) * N_GRID;
            const int n0 = nt * 128 + h * 64 + p * 32 + cg;
#pragma unroll
            for (int i = 0; i < 2; i++) {
                float4 e = *(const float4*)(pe + i * 4);
                float4 o = *(const float4*)(po + i * 4);
                int c = n0 + i * 4;
                *(float4*)(rowp + c) = make_float4(e.x + o.x, e.y + o.y, e.z + o.z, e.w + o.w);
                *(float4*)(rowp + (4092 - c)) = make_float4(e.w - o.w, e.z - o.z, e.y - o.y, e.x - o.x);
            }
        }
        __syncthreads();                // X reads done before refill
        if (h == 0) fill_B(sb, 1, nt, 1, 1, tid);                 // prefetch h1kc1 -> buf1
    }
}

// ---------------------------------------------------------------------------
extern "C" void kernel_launch(void* const* d_in, const int* in_sizes, int n_in,
                              void* d_out, int out_size) {
    const float* rho = (const float*)d_in[0];
    const float* ms  = (const float*)d_in[1];
    float* phi = (float*)d_out;
    const int Brows = in_sizes[0] / N_GRID;

    cudaFuncSetAttribute(gemm1_hmma, cudaFuncAttributeMaxDynamicSharedMemorySize, SMEM1_BYTES);
    cudaFuncSetAttribute(gemm2_hmma, cudaFuncAttributeMaxDynamicSharedMemorySize, SMEM2_BYTES);

    prep_kernel<<<6144, 256>>>(rho);

    dim3 g1(Brows / 128, 2, SPLITS);
    gemm1_hmma<<<g1, 512, SMEM1_BYTES>>>(Brows);

    dim3 gr((Brows * 128) / 256, 2);
    reduce_lam_kernel<<<gr, 256>>>(ms, Brows);

    dim3 g2(Brows / 128, NH / 128);
    gemm2_hmma<<<g2, 512, SMEM2_BYTES>>>(phi);
}

// round 8
// speedup vs baseline: 3.9928x; 1.1637x over previous
#include <cuda_runtime.h>
#include <cuda_bf16.h>
#include <math.h>
#include <stdint.h>

#define N_GRID 4096
#define NH     2048
#define SPLITS 8
#define MAXB   1024

// ---------------- device scratch ----------------
__device__ __nv_bfloat16 g_uP_hi[MAXB * NH];
__device__ __nv_bfloat16 g_uP_lo[MAXB * NH];
__device__ __nv_bfloat16 g_uM_hi[MAXB * NH];
__device__ __nv_bfloat16 g_uM_lo[MAXB * NH];
__device__ __nv_bfloat16 g_CsF_hi[2 * 128 * NH];
__device__ __nv_bfloat16 g_CsF_lo[2 * 128 * NH];
__device__ __nv_bfloat16 g_CsT_hi[2 * NH * 128];
__device__ __nv_bfloat16 g_CsT_lo[2 * NH * 128];
__device__ float         g_part  [16 * MAXB * 128];
__device__ __nv_bfloat16 g_Ae_hi[MAXB * 128];
__device__ __nv_bfloat16 g_Ae_lo[MAXB * 128];
__device__ __nv_bfloat16 g_Ao_hi[MAXB * 128];
__device__ __nv_bfloat16 g_Ao_lo[MAXB * 128];

// ---------------- helpers ----------------
__device__ __forceinline__ uint32_t smem_u32(const void* p) {
    uint32_t a;
    asm("{ .reg .u64 t; cvta.to.shared.u64 t, %1; cvt.u32.u64 %0, t; }" : "=r"(a) : "l"(p));
    return a;
}
__device__ __forceinline__ uint32_t swz(uint32_t off) { return off ^ ((off >> 3) & 0x70); }

__device__ __forceinline__ void cp16(uint32_t dst, const void* src) {
    asm volatile("cp.async.cg.shared.global [%0], [%1], 16;" :: "r"(dst), "l"(src));
}
__device__ __forceinline__ void cp_commit() {
    asm volatile("cp.async.commit_group;" ::: "memory");
}
template <int N>
__device__ __forceinline__ void cp_wait() {
    asm volatile("cp.async.wait_group %0;" :: "n"(N) : "memory");
}

__device__ __forceinline__ void ldsm_x4(uint32_t& r0, uint32_t& r1, uint32_t& r2, uint32_t& r3,
                                        uint32_t addr) {
    asm volatile("ldmatrix.sync.aligned.m8n8.x4.shared.b16 {%0,%1,%2,%3}, [%4];"
                 : "=r"(r0), "=r"(r1), "=r"(r2), "=r"(r3) : "r"(addr));
}
__device__ __forceinline__ void ldsm_x2(uint32_t& r0, uint32_t& r1, uint32_t addr) {
    asm volatile("ldmatrix.sync.aligned.m8n8.x2.shared.b16 {%0,%1}, [%2];"
                 : "=r"(r0), "=r"(r1) : "r"(addr));
}
__device__ __forceinline__ void mma_bf16(float* c, uint32_t a0, uint32_t a1, uint32_t a2,
                                         uint32_t a3, uint32_t b0, uint32_t b1) {
    asm volatile("mma.sync.aligned.m16n8k16.row.col.f32.bf16.bf16.f32 "
                 "{%0,%1,%2,%3}, {%4,%5,%6,%7}, {%8,%9}, {%0,%1,%2,%3};"
                 : "+f"(c[0]), "+f"(c[1]), "+f"(c[2]), "+f"(c[3])
                 : "r"(a0), "r"(a1), "r"(a2), "r"(a3), "r"(b0), "r"(b1));
}

__device__ __forceinline__ void split2(float v, __nv_bfloat16& h, __nv_bfloat16& l) {
    h = __float2bfloat16(v);
    l = __float2bfloat16(v - __bfloat162float(h));
}

// ---------------------------------------------------------------------------
__device__ __forceinline__ float cos_acc(float x) {
    const float INV_PIO2 = 0.6366197723675814f;
    float qf = rintf(x * INV_PIO2);
    int   iq = (int)qf;
    const float HI = 1.57079637050628662109375f;
    const float MD = -4.3711388286737929e-08f;
    const float LO = -1.7151245100059657e-15f;
    float r = fmaf(-qf, HI, x);
    r = fmaf(-qf, MD, r);
    r = fmaf(-qf, LO, r);
    float r2 = r * r;
    float pc = fmaf(r2,  2.4390448796e-05f, -1.3886763775e-03f);
    pc = fmaf(r2, pc,  4.1666623323e-02f);
    pc = fmaf(r2, pc, -4.9999999725e-01f);
    pc = fmaf(r2, pc,  1.0f);
    float ps = fmaf(r2,  2.7183114939e-06f, -1.9839334836e-04f);
    ps = fmaf(r2, ps,  8.3333293859e-03f);
    ps = fmaf(r2, ps, -1.6666666642e-01f);
    ps = r * fmaf(r2, ps, 1.0f);
    int n = iq & 3;
    float v = (n & 1) ? ps : pc;
    if (n == 1 || n == 2) v = -v;
    return v;
}

__device__ __forceinline__ float cs_val(int n, int k) {
    const float PI_F = 3.1415927410125732421875f;
    float t1 = PI_F * (float)(2 * n + 1);
    float theta = (t1 * (float)k) * (1.0f / 8192.0f);
    const float SCALE = 0.02209708691f;
    return SCALE * cos_acc(theta);
}

// ---------------------------------------------------------------------------
// prep: fold rho; build folded Cs tables.
// Exact identity: cos(pi*k - x) = (-1)^k cos(x)  =>  folded value = cs_val(n',k)
// ---------------------------------------------------------------------------
__global__ void prep_kernel(const float* __restrict__ rho) {
    int bx = blockIdx.x;
    if (bx < 2048) {
        int t = bx * 256 + threadIdx.x;
        int b = t >> 9;
        int np = (t & 511) * 4;
        float4 f = *(const float4*)(rho + (size_t)b * N_GRID + np);
        float4 r = *(const float4*)(rho + (size_t)b * N_GRID + (4092 - np));
        float up[4] = {f.x + r.w, f.y + r.z, f.z + r.y, f.w + r.x};
        float um[4] = {f.x - r.w, f.y - r.z, f.z - r.y, f.w - r.x};
        __nv_bfloat16 ph[4], pl[4], mh[4], ml[4];
#pragma unroll
        for (int j = 0; j < 4; j++) { split2(up[j], ph[j], pl[j]); split2(um[j], mh[j], ml[j]); }
        ((uint2*)g_uP_hi)[t] = *(uint2*)ph;
        ((uint2*)g_uP_lo)[t] = *(uint2*)pl;
        ((uint2*)g_uM_hi)[t] = *(uint2*)mh;
        ((uint2*)g_uM_lo)[t] = *(uint2*)ml;
    } else if (bx < 4096) {
        int t = (bx - 2048) * 256 + threadIdx.x;
        int g = t >> 18;
        int rem = t & 0x3FFFF;
        int kp = rem >> 11, np = rem & (NH - 1);
        int k = g ? (2 * kp + 1) : (2 * kp + 2);
        float v = cs_val(np, k);
        __nv_bfloat16 h, l;
        split2(v, h, l);
        g_CsF_hi[t] = h; g_CsF_lo[t] = l;
    } else {
        int t = (bx - 4096) * 256 + threadIdx.x;
        int g = t >> 18;
        int rem = t & 0x3FFFF;
        int np = rem >> 7, kp = rem & 127;
        int k = g ? (2 * kp + 1) : (2 * kp + 2);
        float v = cs_val(np, k);
        __nv_bfloat16 h, l;
        split2(v, h, l);
        g_CsT_hi[t] = h; g_CsT_lo[t] = l;
    }
}

// ---------------------------------------------------------------------------
__device__ __forceinline__ void tile_async(uint32_t dst, const __nv_bfloat16* src,
                                           int stride, int tid) {          // 128x64
    const int row = tid >> 2;
    const int c0 = tid & 3;
    const char* s = (const char*)(src + (size_t)row * stride);
#pragma unroll
    for (int i = 0; i < 2; i++) {
        int ch = c0 + i * 4;
        cp16(dst + swz((uint32_t)row * 128 + ch * 16), s + ch * 16);
    }
}
__device__ __forceinline__ void tile_async64(uint32_t dst, const __nv_bfloat16* src,
                                             int stride, int tid) {        // 64x64
    const int row = tid >> 3;
    const int ch = tid & 7;
    cp16(dst + swz((uint32_t)row * 128 + ch * 16), (const char*)(src + (size_t)row * stride) + ch * 16);
}

// one 64-wide K step; warp tile 32x32; term-outer MMA ordering
template <int ALO, int BLO>
__device__ __forceinline__ void compute_step(uint32_t aB, uint32_t bB, int wm, int wn,
                                             int lane, float acc[2][4][4]) {
    const uint32_t aRow = (uint32_t)(wm * 32 + (lane & 15)) * 128 + ((lane >> 4) << 4);
    const uint32_t bRow = (uint32_t)(wn * 32 + (lane & 7)) * 128 + (((lane >> 3) & 1) << 4);
#pragma unroll
    for (int k16 = 0; k16 < 4; k16++) {
        const uint32_t kb = k16 * 32;
        uint32_t aH[2][4], aL[2][4];
#pragma unroll
        for (int mi = 0; mi < 2; mi++) {
            uint32_t off = swz(aRow + mi * 16 * 128 + kb);
            ldsm_x4(aH[mi][0], aH[mi][1], aH[mi][2], aH[mi][3], aB + off);
            ldsm_x4(aL[mi][0], aL[mi][1], aL[mi][2], aL[mi][3], aB + ALO + off);
        }
        uint32_t bH[4][2], bL[4][2];
#pragma unroll
        for (int nj = 0; nj < 4; nj++) {
            uint32_t off = swz(bRow + nj * 8 * 128 + kb);
            ldsm_x2(bH[nj][0], bH[nj][1], bB + off);
            ldsm_x2(bL[nj][0], bL[nj][1], bB + BLO + off);
        }
        // term-outer: 8 independent MMAs per term
#pragma unroll
        for (int mi = 0; mi < 2; mi++)
#pragma unroll
            for (int nj = 0; nj < 4; nj++)
                mma_bf16(acc[mi][nj], aH[mi][0], aH[mi][1], aH[mi][2], aH[mi][3], bH[nj][0], bH[nj][1]);
#pragma unroll
        for (int mi = 0; mi < 2; mi++)
#pragma unroll
            for (int nj = 0; nj < 4; nj++)
                mma_bf16(acc[mi][nj], aH[mi][0], aH[mi][1], aH[mi][2], aH[mi][3], bL[nj][0], bL[nj][1]);
#pragma unroll
        for (int mi = 0; mi < 2; mi++)
#pragma unroll
            for (int nj = 0; nj < 4; nj++)
                mma_bf16(acc[mi][nj], aL[mi][0], aL[mi][1], aL[mi][2], aL[mi][3], bH[nj][0], bH[nj][1]);
    }
}

// ---------------------------------------------------------------------------
// GEMM1: 3-stage ring, one sync per step. grid (8, 2, SPLITS), block 512.
// stage 64KB: AH 0, AL 16K, BH 32K, BL 48K
// ---------------------------------------------------------------------------
#define STG1 65536
#define SMEM1_BYTES (3 * STG1)

__global__ __launch_bounds__(512) void gemm1_hmma(int Brows) {
    extern __shared__ char sm[];
    const uint32_t sb = smem_u32(sm);
    const int tid = threadIdx.x, wid = tid >> 5, lane = tid & 31;
    const int wm = wid & 3, wn = wid >> 2;
    const int mt = blockIdx.x, grp = blockIdx.y, sp = blockIdx.z;
    const int k0 = sp * (NH / SPLITS);
    const int NS = (NH / SPLITS) / 64;               // 4

    float acc[2][4][4];
#pragma unroll
    for (int a = 0; a < 2; a++)
#pragma unroll
        for (int b = 0; b < 4; b++)
#pragma unroll
            for (int c = 0; c < 4; c++) acc[a][b][c] = 0.0f;

    const __nv_bfloat16* aHsrc = (grp ? g_uM_hi : g_uP_hi) + (size_t)(mt * 128) * NH + k0;
    const __nv_bfloat16* aLsrc = (grp ? g_uM_lo : g_uP_lo) + (size_t)(mt * 128) * NH + k0;
    const __nv_bfloat16* bHsrc = g_CsF_hi + (size_t)grp * 128 * NH + k0;
    const __nv_bfloat16* bLsrc = g_CsF_lo + (size_t)grp * 128 * NH + k0;

#define G1FILL(slot, ko)                                          \
    do {                                                          \
        uint32_t st_ = sb + (slot) * STG1;                        \
        tile_async(st_,         aHsrc + (ko), NH, tid);           \
        tile_async(st_ + 16384, aLsrc + (ko), NH, tid);           \
        tile_async(st_ + 32768, bHsrc + (ko), NH, tid);           \
        tile_async(st_ + 49152, bLsrc + (ko), NH, tid);           \
        cp_commit();                                              \
    } while (0)

    G1FILL(0, 0);
    G1FILL(1, 64);
    for (int s = 0; s < NS; s++) {
        if (s + 2 < NS) cp_wait<1>(); else if (s + 1 < NS) cp_wait<1>(); else cp_wait<0>();
        __syncthreads();
        if (s + 2 < NS) {
            int slot = (s + 2) % 3;
            G1FILL(slot, (s + 2) * 64);
        }
        uint32_t st = sb + (s % 3) * STG1;
        compute_step<16384, 16384>(st, st + 32768, wm, wn, lane, acc);
    }

    const int g = lane >> 2, tig = lane & 3;
    const int mbase = mt * 128 + wm * 32;
    const int nbase = wn * 32;
#pragma unroll
    for (int mi = 0; mi < 2; mi++)
#pragma unroll
        for (int nj = 0; nj < 4; nj++) {
            int row = mbase + mi * 16 + g;
            int col = nbase + nj * 8 + tig * 2;
            float* p0 = g_part + ((size_t)(grp * SPLITS + sp) * Brows + row) * 128 + col;
            *(float2*)p0             = make_float2(acc[mi][nj][0], acc[mi][nj][1]);
            *(float2*)(p0 + 8 * 128) = make_float2(acc[mi][nj][2], acc[mi][nj][3]);
        }
}

__global__ void reduce_lam_kernel(const float* __restrict__ ms, int Brows) {
    int g = blockIdx.y;
    int idx = blockIdx.x * blockDim.x + threadIdx.x;
    int kp = idx & 127;
    float sum = 0.0f;
#pragma unroll
    for (int s = 0; s < SPLITS; s++)
        sum += g_part[(size_t)(g * SPLITS + s) * Brows * 128 + idx];
    float v = ms[g ? (2 * kp) : (2 * kp + 1)] * sum;
    __nv_bfloat16 h, l;
    split2(v, h, l);
    if (g) { g_Ao_hi[idx] = h; g_Ao_lo[idx] = l; }
    else   { g_Ae_hi[idx] = h; g_Ae_lo[idx] = l; }
}

// ---------------------------------------------------------------------------
// GEMM2 v3: grid (8, 16), block 512. Warp (wm 0..3, wn 0..3): 32 rows x 16
// cols, DUAL e/o accumulators; epilogue is register-local e±o -> direct STG.
// smem 192KB: A resident 128KB: region(eo,op) = (eo*2+op)*32768, kc*16384 in.
// B (one 64-col half, both kc): B_BASE + (eo*2+op)*16384 + kc*8192, 64KB.
// 3 __syncthreads total.
// ---------------------------------------------------------------------------
#define B_BASE 131072
#define SMEM2_BYTES 196608

__device__ __forceinline__ void fill_B2(uint32_t sb, int nt, int h, int tid) {
#pragma unroll
    for (int kc = 0; kc < 2; kc++) {
        size_t be = ((size_t)(nt * 128 + h * 64)) * 128 + kc * 64;
        size_t bo = (size_t)NH * 128 + be;
        tile_async64(sb + B_BASE +         kc * 8192, g_CsT_hi + be, 128, tid);
        tile_async64(sb + B_BASE + 16384 + kc * 8192, g_CsT_lo + be, 128, tid);
        tile_async64(sb + B_BASE + 32768 + kc * 8192, g_CsT_hi + bo, 128, tid);
        tile_async64(sb + B_BASE + 49152 + kc * 8192, g_CsT_lo + bo, 128, tid);
    }
    cp_commit();
}

__global__ __launch_bounds__(512) void gemm2_hmma(float* __restrict__ phi) {
    extern __shared__ char sm[];
    const uint32_t sb = smem_u32(sm);
    const int tid = threadIdx.x, wid = tid >> 5, lane = tid & 31;
    const int wm = wid & 3, wn = wid >> 2;
    const int mt = blockIdx.x, nt = blockIdx.y;

    // A resident fill (8 tiles = 128KB): region(eo,op) + kc*16K
    {
        const size_t aoff = (size_t)(mt * 128) * 128;
#pragma unroll
        for (int kc = 0; kc < 2; kc++) {
            tile_async(sb +          kc * 16384, g_Ae_hi + aoff + kc * 64, 128, tid);
            tile_async(sb + 32768 +  kc * 16384, g_Ae_lo + aoff + kc * 64, 128, tid);
            tile_async(sb + 65536 +  kc * 16384, g_Ao_hi + aoff + kc * 64, 128, tid);
            tile_async(sb + 98304 +  kc * 16384, g_Ao_lo + aoff + kc * 64, 128, tid);
        }
        cp_commit();
    }
    fill_B2(sb, nt, 0, tid);

    const uint32_t aRow = (uint32_t)(wm * 32 + (lane & 15)) * 128 + ((lane >> 4) << 4);
    const uint32_t bRow = (uint32_t)(wn * 16 + (lane & 7)) * 128 + (((lane >> 3) & 1) << 4);
    const int g = lane >> 2, tig = lane & 3;

    for (int h = 0; h < 2; h++) {
        float acc[2][2][2][4];                       // [eo][mi][nj][4]
#pragma unroll
        for (int e = 0; e < 2; e++)
#pragma unroll
            for (int a = 0; a < 2; a++)
#pragma unroll
                for (int b = 0; b < 2; b++)
#pragma unroll
                    for (int c = 0; c < 4; c++) acc[e][a][b][c] = 0.0f;

        cp_wait<0>();
        __syncthreads();

#pragma unroll
        for (int kc = 0; kc < 2; kc++) {
#pragma unroll
            for (int k16 = 0; k16 < 4; k16++) {
                const uint32_t kb = k16 * 32;
#pragma unroll
                for (int eo = 0; eo < 2; eo++) {
                    uint32_t aBase = sb + eo * 65536u + kc * 16384u;
                    uint32_t bBase = sb + B_BASE + eo * 32768u + kc * 8192u;
                    uint32_t aH[2][4], aL[2][4];
#pragma unroll
                    for (int mi = 0; mi < 2; mi++) {
                        uint32_t off = swz(aRow + mi * 16 * 128 + kb);
                        ldsm_x4(aH[mi][0], aH[mi][1], aH[mi][2], aH[mi][3], aBase + off);
                        ldsm_x4(aL[mi][0], aL[mi][1], aL[mi][2], aL[mi][3], aBase + 32768u + off);
                    }
                    uint32_t bH[2][2], bL[2][2];
#pragma unroll
                    for (int nj = 0; nj < 2; nj++) {
                        uint32_t off = swz(bRow + nj * 8 * 128 + kb);
                        ldsm_x2(bH[nj][0], bH[nj][1], bBase + off);
                        ldsm_x2(bL[nj][0], bL[nj][1], bBase + 16384u + off);
                    }
#pragma unroll
                    for (int mi = 0; mi < 2; mi++)
#pragma unroll
                        for (int nj = 0; nj < 2; nj++)
                            mma_bf16(acc[eo][mi][nj], aH[mi][0], aH[mi][1], aH[mi][2], aH[mi][3],
                                     bH[nj][0], bH[nj][1]);
#pragma unroll
                    for (int mi = 0; mi < 2; mi++)
#pragma unroll
                        for (int nj = 0; nj < 2; nj++)
                            mma_bf16(acc[eo][mi][nj], aH[mi][0], aH[mi][1], aH[mi][2], aH[mi][3],
                                     bL[nj][0], bL[nj][1]);
#pragma unroll
                    for (int mi = 0; mi < 2; mi++)
#pragma unroll
                        for (int nj = 0; nj < 2; nj++)
                            mma_bf16(acc[eo][mi][nj], aL[mi][0], aL[mi][1], aL[mi][2], aL[mi][3],
                                     bH[nj][0], bH[nj][1]);
                }
            }
        }
        __syncthreads();                 // all warps done reading B(h)
        if (h == 0) fill_B2(sb, nt, 1, tid);

        // register epilogue: phi[n'] = e + o ; phi[4095-n'] = e - o
#pragma unroll
        for (int mi = 0; mi < 2; mi++)
#pragma unroll
            for (int nj = 0; nj < 2; nj++) {
#pragma unroll
                for (int half = 0; half < 2; half++) {
                    int row = mt * 128 + wm * 32 + mi * 16 + half * 8 + g;
                    int c = nt * 128 + h * 64 + wn * 16 + nj * 8 + tig * 2;
                    float e0 = acc[0][mi][nj][half * 2];
                    float e1 = acc[0][mi][nj][half * 2 + 1];
                    float o0 = acc[1][mi][nj][half * 2];
                    float o1 = acc[1][mi][nj][half * 2 + 1];
                    float* rowp = phi + (size_t)row * N_GRID;
                    *(float2*)(rowp + c) = make_float2(e0 + o0, e1 + o1);
                    *(float2*)(rowp + (4094 - c)) = make_float2(e1 - o1, e0 - o0);
                }
            }
    }
}

// ---------------------------------------------------------------------------
extern "C" void kernel_launch(void* const* d_in, const int* in_sizes, int n_in,
                              void* d_out, int out_size) {
    const float* rho = (const float*)d_in[0];
    const float* ms  = (const float*)d_in[1];
    float* phi = (float*)d_out;
    const int Brows = in_sizes[0] / N_GRID;

    cudaFuncSetAttribute(gemm1_hmma, cudaFuncAttributeMaxDynamicSharedMemorySize, SMEM1_BYTES);
    cudaFuncSetAttribute(gemm2_hmma, cudaFuncAttributeMaxDynamicSharedMemorySize, SMEM2_BYTES);

    prep_kernel<<<6144, 256>>>(rho);

    dim3 g1(Brows / 128, 2, SPLITS);
    gemm1_hmma<<<g1, 512, SMEM1_BYTES>>>(Brows);

    dim3 gr((Brows * 128) / 256, 2);
    reduce_lam_kernel<<<gr, 256>>>(ms, Brows);

    dim3 g2(Brows / 128, NH / 128);
    gemm2_hmma<<<g2, 512, SMEM2_BYTES>>>(phi);
}